// round 1
// baseline (speedup 1.0000x reference)
#include <cuda_runtime.h>
#include <mma.h>
#include <math.h>
#include <stdint.h>

using namespace nvcuda;

#define N_EMBD 1024
#define NHEAD  16
#define HDIM   64
#define HID    2730
#define BT     4096   // B*T rows
#define TS     2048   // sequence length
#define LN_EPS 1e-5f

// ---------------- scratch (device globals; no allocation allowed) ----------
__device__ float g_h   [(size_t)BT * N_EMBD];      // LN output (h1 then h2)
__device__ float g_qkv [(size_t)BT * 3 * N_EMBD];
__device__ float g_att [(size_t)BT * N_EMBD];
__device__ float g_x2  [(size_t)BT * N_EMBD];
__device__ float g_gate[(size_t)BT * HID];
__device__ float g_ff  [(size_t)BT * HID];

// ---------------- LayerNorm ------------------------------------------------
// one block per row, 256 threads * float4 = 1024 cols
__global__ void __launch_bounds__(256) ln_kernel(
    const float* __restrict__ x, const float* __restrict__ g,
    const float* __restrict__ b, float* __restrict__ out)
{
    int row = blockIdx.x;
    int tid = threadIdx.x;
    const float4* xr = (const float4*)(x + (size_t)row * N_EMBD);
    float4 v = xr[tid];
    float s  = v.x + v.y + v.z + v.w;
    float ss = v.x*v.x + v.y*v.y + v.z*v.z + v.w*v.w;
    #pragma unroll
    for (int o = 16; o; o >>= 1) {
        s  += __shfl_xor_sync(0xffffffffu, s, o);
        ss += __shfl_xor_sync(0xffffffffu, ss, o);
    }
    __shared__ float red[16];
    int warp = tid >> 5, lane = tid & 31;
    if (lane == 0) { red[warp] = s; red[8 + warp] = ss; }
    __syncthreads();
    if (tid == 0) {
        float a = 0.f, a2 = 0.f;
        #pragma unroll
        for (int i = 0; i < 8; i++) { a += red[i]; a2 += red[8 + i]; }
        red[0] = a; red[8] = a2;
    }
    __syncthreads();
    float mean = red[0] * (1.0f / N_EMBD);
    float var  = red[8] * (1.0f / N_EMBD) - mean * mean;
    float rstd = rsqrtf(var + LN_EPS);
    float4 go = ((const float4*)g)[tid];
    float4 bo = ((const float4*)b)[tid];
    float4 o;
    o.x = (v.x - mean) * rstd * go.x + bo.x;
    o.y = (v.y - mean) * rstd * go.y + bo.y;
    o.z = (v.z - mean) * rstd * go.z + bo.z;
    o.w = (v.w - mean) * rstd * go.w + bo.w;
    ((float4*)(out + (size_t)row * N_EMBD))[tid] = o;
}

// ---------------- Generic TF32 WMMA GEMM ----------------------------------
// C[M,N] = A[M,K] @ B[K,N] + bias, with epilogue variants.
// BM=128, BN=128, BK=16. 256 threads (8 warps, 2x4). Warp tile 64x32.
#define GBM 128
#define GBN 128
#define GBK 16
#define ALD 20
#define BLD 136

enum { EPI_BIAS = 0, EPI_RES = 1, EPI_SILU = 2, EPI_MUL = 3 };

template <int EPI>
__global__ void __launch_bounds__(256) gemm_tf32(
    const float* __restrict__ A, const float* __restrict__ B,
    const float* __restrict__ bias, const float* __restrict__ extra,
    float* __restrict__ C, int M, int N, int K)
{
    __shared__ __align__(16) float As[GBM * ALD];
    __shared__ __align__(16) float Bs[GBK * BLD];
    __shared__ __align__(16) float Es[8 * 256];

    int tid = threadIdx.x;
    int warp = tid >> 5, lane = tid & 31;
    int bm = blockIdx.y * GBM, bn = blockIdx.x * GBN;
    int wm = (warp >> 2) * 64;   // 2 warp-rows
    int wn = (warp & 3) * 32;    // 4 warp-cols

    wmma::fragment<wmma::accumulator, 16, 16, 8, float> acc[4][2];
    #pragma unroll
    for (int i = 0; i < 4; i++)
        #pragma unroll
        for (int j = 0; j < 2; j++)
            wmma::fill_fragment(acc[i][j], 0.0f);

    for (int k0 = 0; k0 < K; k0 += GBK) {
        // load A tile 128x16
        #pragma unroll
        for (int i = tid; i < GBM * GBK; i += 256) {
            int r = i >> 4, c = i & 15;
            int kk = k0 + c;
            As[r * ALD + c] = (kk < K) ? __ldg(&A[(size_t)(bm + r) * K + kk]) : 0.0f;
        }
        // load B tile 16x128
        #pragma unroll
        for (int i = tid; i < GBK * GBN; i += 256) {
            int r = i >> 7, c = i & 127;
            int kk = k0 + r, nn = bn + c;
            Bs[r * BLD + c] = (kk < K && nn < N) ? __ldg(&B[(size_t)kk * N + nn]) : 0.0f;
        }
        __syncthreads();
        #pragma unroll
        for (int ks = 0; ks < 2; ks++) {
            wmma::fragment<wmma::matrix_a, 16, 16, 8, wmma::precision::tf32, wmma::row_major> a[4];
            wmma::fragment<wmma::matrix_b, 16, 16, 8, wmma::precision::tf32, wmma::row_major> bf[2];
            #pragma unroll
            for (int i = 0; i < 4; i++) {
                wmma::load_matrix_sync(a[i], &As[(wm + i * 16) * ALD + ks * 8], ALD);
                #pragma unroll
                for (int t = 0; t < a[i].num_elements; t++)
                    a[i].x[t] = wmma::__float_to_tf32(a[i].x[t]);
            }
            #pragma unroll
            for (int j = 0; j < 2; j++) {
                wmma::load_matrix_sync(bf[j], &Bs[(ks * 8) * BLD + wn + j * 16], BLD);
                #pragma unroll
                for (int t = 0; t < bf[j].num_elements; t++)
                    bf[j].x[t] = wmma::__float_to_tf32(bf[j].x[t]);
            }
            #pragma unroll
            for (int i = 0; i < 4; i++)
                #pragma unroll
                for (int j = 0; j < 2; j++)
                    wmma::mma_sync(acc[i][j], a[i], bf[j], acc[i][j]);
        }
        __syncthreads();
    }

    // epilogue via per-warp smem staging (handles N boundary)
    float* eb = &Es[warp * 256];
    #pragma unroll
    for (int i = 0; i < 4; i++) {
        #pragma unroll
        for (int j = 0; j < 2; j++) {
            wmma::store_matrix_sync(eb, acc[i][j], 16, wmma::mem_row_major);
            __syncwarp();
            #pragma unroll
            for (int e = lane; e < 256; e += 32) {
                int r = e >> 4, c = e & 15;
                int gr = bm + wm + i * 16 + r;
                int gc = bn + wn + j * 16 + c;
                if (gc < N && gr < M) {
                    float v = eb[e] + bias[gc];
                    if (EPI == EPI_RES)  v += extra[(size_t)gr * N + gc];
                    if (EPI == EPI_SILU) v = v / (1.0f + __expf(-v));
                    if (EPI == EPI_MUL)  v *= extra[(size_t)gr * N + gc];
                    C[(size_t)gr * N + gc] = v;
                }
            }
            __syncwarp();
        }
    }
}

// ---------------- Flash attention (ALiBi + causal) -------------------------
// grid (32 qtiles, 16 heads, 2 batch), 128 threads (4 warps).
// S = (Q*scale) K^T + slope*(q-k); causal mask; online softmax; O += P V.
#define ATLD 68
#define ATT_SMEM ((5 * 64 * ATLD + 3 * 64) * 4)

__global__ void __launch_bounds__(128) attn_kernel(
    const float* __restrict__ qkv, float* __restrict__ out)
{
    extern __shared__ __align__(16) float sm[];
    float* Qs = sm;
    float* Ks = Qs + 64 * ATLD;
    float* Vs = Ks + 64 * ATLD;
    float* Ss = Vs + 64 * ATLD;
    float* Os = Ss + 64 * ATLD;
    float* mrow = Os + 64 * ATLD;
    float* lrow = mrow + 64;
    float* frow = lrow + 64;

    int tid = threadIdx.x, warp = tid >> 5;
    int qt = blockIdx.x, h = blockIdx.y, bb = blockIdx.z;
    int q0 = qt * 64;
    const float scale = 0.125f;  // 1/sqrt(64)
    float slope = exp2f(-0.5f * (float)(h + 1));
    size_t base = (size_t)bb * TS * 3072;

    for (int i = tid; i < 64 * 64; i += 128) {
        int r = i >> 6, d = i & 63;
        Qs[r * ATLD + d] = qkv[base + (size_t)(q0 + r) * 3072 + h * 64 + d] * scale;
        Os[r * ATLD + d] = 0.0f;
    }
    if (tid < 64) { mrow[tid] = -1e30f; lrow[tid] = 0.0f; }
    __syncthreads();

    for (int kb = 0; kb <= qt; kb++) {
        int k0 = kb * 64;
        for (int i = tid; i < 64 * 64; i += 128) {
            int r = i >> 6, d = i & 63;
            size_t ro = base + (size_t)(k0 + r) * 3072 + h * 64 + d;
            Ks[r * ATLD + d] = qkv[ro + 1024];
            Vs[r * ATLD + d] = qkv[ro + 2048];
        }
        __syncthreads();

        // S = Q K^T  (each warp owns 16 q-rows)
        {
            int wm = warp * 16;
            wmma::fragment<wmma::accumulator, 16, 16, 8, float> c[4];
            #pragma unroll
            for (int n = 0; n < 4; n++) wmma::fill_fragment(c[n], 0.0f);
            #pragma unroll
            for (int ks = 0; ks < 8; ks++) {
                wmma::fragment<wmma::matrix_a, 16, 16, 8, wmma::precision::tf32, wmma::row_major> a;
                wmma::load_matrix_sync(a, &Qs[wm * ATLD + ks * 8], ATLD);
                #pragma unroll
                for (int t = 0; t < a.num_elements; t++) a.x[t] = wmma::__float_to_tf32(a.x[t]);
                #pragma unroll
                for (int n = 0; n < 4; n++) {
                    wmma::fragment<wmma::matrix_b, 16, 16, 8, wmma::precision::tf32, wmma::col_major> bfr;
                    wmma::load_matrix_sync(bfr, &Ks[(n * 16) * ATLD + ks * 8], ATLD);
                    #pragma unroll
                    for (int t = 0; t < bfr.num_elements; t++) bfr.x[t] = wmma::__float_to_tf32(bfr.x[t]);
                    wmma::mma_sync(c[n], a, bfr, c[n]);
                }
            }
            #pragma unroll
            for (int n = 0; n < 4; n++)
                wmma::store_matrix_sync(&Ss[wm * ATLD + n * 16], c[n], ATLD, wmma::mem_row_major);
        }
        __syncthreads();

        // online softmax: 2 threads per row, 32 cols each
        {
            int r = tid >> 1, half = tid & 1, cb = half * 32;
            int qpos = q0 + r;
            float mold = mrow[r];
            __syncwarp();
            float sv[32];
            float mloc = -1e30f;
            #pragma unroll
            for (int c = 0; c < 32; c++) {
                int kpos = k0 + cb + c;
                float s = Ss[r * ATLD + cb + c] + slope * (float)(qpos - kpos);
                if (kpos > qpos) s = -1e30f;
                sv[c] = s;
                mloc = fmaxf(mloc, s);
            }
            mloc = fmaxf(mloc, __shfl_xor_sync(0xffffffffu, mloc, 1));
            float mnew = fmaxf(mold, mloc);
            float factor = __expf(mold - mnew);
            float ps = 0.0f;
            #pragma unroll
            for (int c = 0; c < 32; c++) {
                float p = __expf(sv[c] - mnew);
                Ss[r * ATLD + cb + c] = p;
                ps += p;
            }
            ps += __shfl_xor_sync(0xffffffffu, ps, 1);
            if (!half) {
                mrow[r] = mnew;
                lrow[r] = lrow[r] * factor + ps;
                frow[r] = factor;
            }
        }
        __syncthreads();

        // rescale O
        for (int i = tid; i < 64 * 64; i += 128) {
            int r = i >> 6, d = i & 63;
            Os[r * ATLD + d] *= frow[r];
        }
        __syncthreads();

        // O += P @ V
        {
            int wm = warp * 16;
            wmma::fragment<wmma::accumulator, 16, 16, 8, float> c[4];
            #pragma unroll
            for (int n = 0; n < 4; n++)
                wmma::load_matrix_sync(c[n], &Os[wm * ATLD + n * 16], ATLD, wmma::mem_row_major);
            #pragma unroll
            for (int ks = 0; ks < 8; ks++) {
                wmma::fragment<wmma::matrix_a, 16, 16, 8, wmma::precision::tf32, wmma::row_major> a;
                wmma::load_matrix_sync(a, &Ss[wm * ATLD + ks * 8], ATLD);
                #pragma unroll
                for (int t = 0; t < a.num_elements; t++) a.x[t] = wmma::__float_to_tf32(a.x[t]);
                #pragma unroll
                for (int n = 0; n < 4; n++) {
                    wmma::fragment<wmma::matrix_b, 16, 16, 8, wmma::precision::tf32, wmma::row_major> bfr;
                    wmma::load_matrix_sync(bfr, &Vs[(ks * 8) * ATLD + n * 16], ATLD);
                    #pragma unroll
                    for (int t = 0; t < bfr.num_elements; t++) bfr.x[t] = wmma::__float_to_tf32(bfr.x[t]);
                    wmma::mma_sync(c[n], a, bfr, c[n]);
                }
            }
            #pragma unroll
            for (int n = 0; n < 4; n++)
                wmma::store_matrix_sync(&Os[wm * ATLD + n * 16], c[n], ATLD, wmma::mem_row_major);
        }
        __syncthreads();
    }

    for (int i = tid; i < 64 * 64; i += 128) {
        int r = i >> 6, d = i & 63;
        out[(size_t)(bb * TS + q0 + r) * N_EMBD + h * 64 + d] = Os[r * ATLD + d] / lrow[r];
    }
}

// ---------------- launch ---------------------------------------------------
extern "C" void kernel_launch(void* const* d_in, const int* in_sizes, int n_in,
                              void* d_out, int out_size)
{
    (void)in_sizes; (void)n_in; (void)out_size;
    const float* x      = (const float*)d_in[0];
    const float* ln1_g  = (const float*)d_in[1];
    const float* ln1_b  = (const float*)d_in[2];
    const float* qkv_w  = (const float*)d_in[3];
    const float* qkv_b  = (const float*)d_in[4];
    const float* proj_w = (const float*)d_in[5];
    const float* proj_b = (const float*)d_in[6];
    const float* ln2_g  = (const float*)d_in[7];
    const float* ln2_b  = (const float*)d_in[8];
    const float* gate_w = (const float*)d_in[9];
    const float* gate_b = (const float*)d_in[10];
    const float* up_w   = (const float*)d_in[11];
    const float* up_b   = (const float*)d_in[12];
    const float* down_w = (const float*)d_in[13];
    const float* down_b = (const float*)d_in[14];
    float* out = (float*)d_out;

    float *h, *qkv, *att, *x2, *gate, *ff;
    cudaGetSymbolAddress((void**)&h,    g_h);
    cudaGetSymbolAddress((void**)&qkv,  g_qkv);
    cudaGetSymbolAddress((void**)&att,  g_att);
    cudaGetSymbolAddress((void**)&x2,   g_x2);
    cudaGetSymbolAddress((void**)&gate, g_gate);
    cudaGetSymbolAddress((void**)&ff,   g_ff);

    cudaFuncSetAttribute(attn_kernel, cudaFuncAttributeMaxDynamicSharedMemorySize, ATT_SMEM);

    // 1) LN1
    ln_kernel<<<BT, 256>>>(x, ln1_g, ln1_b, h);
    // 2) qkv = h @ qkv_w + b
    {
        dim3 g((3 * N_EMBD + GBN - 1) / GBN, BT / GBM);
        gemm_tf32<EPI_BIAS><<<g, 256>>>(h, qkv_w, qkv_b, nullptr, qkv, BT, 3 * N_EMBD, N_EMBD);
    }
    // 3) attention
    {
        dim3 g(TS / 64, NHEAD, 2);
        attn_kernel<<<g, 128, ATT_SMEM>>>(qkv, att);
    }
    // 4) x2 = att @ proj_w + b + x
    {
        dim3 g(N_EMBD / GBN, BT / GBM);
        gemm_tf32<EPI_RES><<<g, 256>>>(att, proj_w, proj_b, x, x2, BT, N_EMBD, N_EMBD);
    }
    // 5) LN2
    ln_kernel<<<BT, 256>>>(x2, ln2_g, ln2_b, h);
    // 6) gate = silu(h @ gate_w + b)
    {
        dim3 g((HID + GBN - 1) / GBN, BT / GBM);
        gemm_tf32<EPI_SILU><<<g, 256>>>(h, gate_w, gate_b, nullptr, gate, BT, HID, N_EMBD);
        // 7) ff = (h @ up_w + b) * gate
        gemm_tf32<EPI_MUL><<<g, 256>>>(h, up_w, up_b, gate, ff, BT, HID, N_EMBD);
    }
    // 8) out = ff @ down_w + b + x2
    {
        dim3 g(N_EMBD / GBN, BT / GBM);
        gemm_tf32<EPI_RES><<<g, 256>>>(ff, down_w, down_b, x2, out, BT, N_EMBD, HID);
    }
}

// round 2
// speedup vs baseline: 1.6120x; 1.6120x over previous
#include <cuda_runtime.h>
#include <mma.h>
#include <math.h>
#include <stdint.h>

using namespace nvcuda;

#define N_EMBD 1024
#define NHEAD  16
#define HID    2730
#define FF_LD  2752   // padded stride for gate/ff scratch (16B-aligned rows, mult of 32)
#define BT     4096
#define TS     2048
#define LN_EPS 1e-5f

// ---------------- scratch ---------------------------------------------------
__device__ float g_h   [(size_t)BT * N_EMBD];
__device__ float g_qkv [(size_t)BT * 3 * N_EMBD];
__device__ float g_att [(size_t)BT * N_EMBD];
__device__ float g_x2  [(size_t)BT * N_EMBD];
__device__ float g_gate[(size_t)BT * FF_LD];   // pad cols stay zero forever
__device__ float g_ff  [(size_t)BT * FF_LD];

// ---------------- helpers ----------------------------------------------------
__device__ __forceinline__ void cp16(uint32_t dst, const void* src) {
    asm volatile("cp.async.cg.shared.global [%0], [%1], 16;\n" :: "r"(dst), "l"(src));
}
__device__ __forceinline__ void cp16p(uint32_t dst, const void* src, int pb) {
    asm volatile("cp.async.cg.shared.global [%0], [%1], 16, %2;\n" :: "r"(dst), "l"(src), "r"(pb));
}
__device__ __forceinline__ void cp8p(uint32_t dst, const void* src, int pb) {
    asm volatile("cp.async.ca.shared.global [%0], [%1], 8, %2;\n" :: "r"(dst), "l"(src), "r"(pb));
}
#define CP_COMMIT() asm volatile("cp.async.commit_group;\n")
#define CP_WAIT1()  asm volatile("cp.async.wait_group 1;\n")

// fast 2^t for t <= 0 (5-FMA poly, no MUFU)
__device__ __forceinline__ float fexp2(float t) {
    t = fmaxf(t, -126.0f);
    float r = t + 12582912.0f;                 // round-to-nearest magic
    int   fi = __float_as_int(r) - 0x4B400000; // (int)round(t)
    float f = t - (r - 12582912.0f);           // frac in [-0.5, 0.5]
    float p = 1.3333558e-3f;
    p = fmaf(p, f, 9.6181291e-3f);
    p = fmaf(p, f, 5.5504109e-2f);
    p = fmaf(p, f, 2.4022651e-1f);
    p = fmaf(p, f, 6.9314718e-1f);
    p = fmaf(p, f, 1.0f);
    return __int_as_float(__float_as_int(p) + (fi << 23));
}
// silu without MUFU: poly exp + 2 Newton reciprocal steps
__device__ __forceinline__ float fsilu(float v) {
    float e = fexp2(-fabsf(v) * 1.4426950408889634f);   // e^{-|v|}
    float d = 1.0f + e;                                  // (1,2]
    float y = 1.4571429f - 0.45714286f * d;
    y = y * (2.0f - d * y);
    y = y * (2.0f - d * y);                              // ~1/d
    float sig = (v >= 0.0f) ? y : (1.0f - y);
    return v * sig;
}

__device__ __forceinline__ void mma8(float* c, const uint32_t* a, uint32_t b0, uint32_t b1) {
    asm volatile(
        "mma.sync.aligned.m16n8k8.row.col.f32.tf32.tf32.f32 "
        "{%0,%1,%2,%3}, {%4,%5,%6,%7}, {%8,%9}, {%0,%1,%2,%3};\n"
        : "+f"(c[0]), "+f"(c[1]), "+f"(c[2]), "+f"(c[3])
        : "r"(a[0]), "r"(a[1]), "r"(a[2]), "r"(a[3]), "r"(b0), "r"(b1));
}
__device__ __forceinline__ uint32_t f2tf32(float x) {
    uint32_t u; asm("cvt.rna.tf32.f32 %0, %1;" : "=r"(u) : "f"(x)); return u;
}

// ---------------- LayerNorm --------------------------------------------------
__global__ void __launch_bounds__(256) ln_kernel(
    const float* __restrict__ x, const float* __restrict__ g,
    const float* __restrict__ b, float* __restrict__ out)
{
    int row = blockIdx.x;
    int tid = threadIdx.x;
    const float4* xr = (const float4*)(x + (size_t)row * N_EMBD);
    float4 v = xr[tid];
    float s  = v.x + v.y + v.z + v.w;
    float ss = v.x*v.x + v.y*v.y + v.z*v.z + v.w*v.w;
    #pragma unroll
    for (int o = 16; o; o >>= 1) {
        s  += __shfl_xor_sync(0xffffffffu, s, o);
        ss += __shfl_xor_sync(0xffffffffu, ss, o);
    }
    __shared__ float red[16];
    int warp = tid >> 5, lane = tid & 31;
    if (lane == 0) { red[warp] = s; red[8 + warp] = ss; }
    __syncthreads();
    if (tid == 0) {
        float a = 0.f, a2 = 0.f;
        #pragma unroll
        for (int i = 0; i < 8; i++) { a += red[i]; a2 += red[8 + i]; }
        red[0] = a; red[8] = a2;
    }
    __syncthreads();
    float mean = red[0] * (1.0f / N_EMBD);
    float var  = red[8] * (1.0f / N_EMBD) - mean * mean;
    float rstd = rsqrtf(var + LN_EPS);
    float4 go = ((const float4*)g)[tid];
    float4 bo = ((const float4*)b)[tid];
    float4 o;
    o.x = (v.x - mean) * rstd * go.x + bo.x;
    o.y = (v.y - mean) * rstd * go.y + bo.y;
    o.z = (v.z - mean) * rstd * go.z + bo.z;
    o.w = (v.w - mean) * rstd * go.w + bo.w;
    ((float4*)(out + (size_t)row * N_EMBD))[tid] = o;
}

// ---------------- TF32 WMMA GEMM, BK=32, double-buffered cp.async -----------
// smem: As 2*128*36, Bs 2*32*136 (floats)
#define GA_ST 4608
#define GB_ST 4352
#define GSMEM ((2*GA_ST + 2*GB_ST) * 4)

enum { EPI_BIAS = 0, EPI_RES = 1, EPI_SILU = 2, EPI_MUL = 3 };

template <int EPI, int BV>
__global__ void __launch_bounds__(256) gemm_tf32(
    const float* __restrict__ A, const float* __restrict__ B,
    const float* __restrict__ bias, const float* __restrict__ extra,
    float* __restrict__ C, int M, int N, int K, int lda, int ldc)
{
    extern __shared__ __align__(16) float sm[];
    float* As = sm;
    float* Bs = sm + 2 * GA_ST;
    uint32_t sA = (uint32_t)__cvta_generic_to_shared(As);
    uint32_t sB = (uint32_t)__cvta_generic_to_shared(Bs);

    int tid = threadIdx.x;
    int warp = tid >> 5, lane = tid & 31;
    int bm = blockIdx.y * 128, bn = blockIdx.x * 128;
    int wm = (warp >> 2) * 64, wn = (warp & 3) * 32;
    int nkt = (K + 31) >> 5;

    wmma::fragment<wmma::accumulator, 16, 16, 8, float> acc[4][2];
    #pragma unroll
    for (int i = 0; i < 4; i++)
        #pragma unroll
        for (int j = 0; j < 2; j++)
            wmma::fill_fragment(acc[i][j], 0.0f);

    auto loadT = [&](int kt) {
        int stg = kt & 1;
        int k0 = kt << 5;
        #pragma unroll
        for (int j = 0; j < 4; j++) {               // A: 128x32, always in-bounds (lda padded)
            int idx = tid + j * 256;
            int r = idx >> 3, c4 = (idx & 7) << 2;
            uint32_t dst = sA + (uint32_t)(stg * GA_ST + r * 36 + c4) * 4u;
            cp16(dst, A + (size_t)(bm + r) * lda + k0 + c4);
        }
        if (BV == 4) {
            #pragma unroll
            for (int j = 0; j < 4; j++) {           // B: 32x128, 16B
                int idx = tid + j * 256;
                int r = idx >> 5, c4 = (idx & 31) << 2;
                int kk = k0 + r, nn = bn + c4;
                int pb = (kk < K && nn < N) ? 16 : 0;
                uint32_t dst = sB + (uint32_t)(stg * GB_ST + r * 136 + c4) * 4u;
                cp16p(dst, B + (size_t)kk * N + nn, pb);
            }
        } else {
            #pragma unroll
            for (int j = 0; j < 8; j++) {           // B: 32x128, 8B (stride-2730 weights)
                int idx = tid + j * 256;
                int r = idx >> 6, c2 = (idx & 63) << 1;
                int kk = k0 + r, nn = bn + c2;
                int pb = (kk < K && nn < N) ? 8 : 0;
                uint32_t dst = sB + (uint32_t)(stg * GB_ST + r * 136 + c2) * 4u;
                cp8p(dst, B + (size_t)kk * N + nn, pb);
            }
        }
    };

    loadT(0);
    CP_COMMIT();
    for (int kt = 0; kt < nkt; kt++) {
        if (kt + 1 < nkt) loadT(kt + 1);
        CP_COMMIT();
        CP_WAIT1();
        __syncthreads();
        const float* Ab = As + (kt & 1) * GA_ST;
        const float* Bb = Bs + (kt & 1) * GB_ST;
        #pragma unroll
        for (int ks = 0; ks < 4; ks++) {
            wmma::fragment<wmma::matrix_a, 16, 16, 8, wmma::precision::tf32, wmma::row_major> a[4];
            wmma::fragment<wmma::matrix_b, 16, 16, 8, wmma::precision::tf32, wmma::row_major> bf[2];
            #pragma unroll
            for (int i = 0; i < 4; i++) {
                wmma::load_matrix_sync(a[i], &Ab[(wm + i * 16) * 36 + ks * 8], 36);
                #pragma unroll
                for (int t = 0; t < a[i].num_elements; t++)
                    a[i].x[t] = wmma::__float_to_tf32(a[i].x[t]);
            }
            #pragma unroll
            for (int j = 0; j < 2; j++) {
                wmma::load_matrix_sync(bf[j], &Bb[(ks * 8) * 136 + wn + j * 16], 136);
                #pragma unroll
                for (int t = 0; t < bf[j].num_elements; t++)
                    bf[j].x[t] = wmma::__float_to_tf32(bf[j].x[t]);
            }
            #pragma unroll
            for (int i = 0; i < 4; i++)
                #pragma unroll
                for (int j = 0; j < 2; j++)
                    wmma::mma_sync(acc[i][j], a[i], bf[j], acc[i][j]);
        }
        __syncthreads();
    }

    // epilogue (reuse smem)
    float* eb = sm + warp * 256;
    #pragma unroll
    for (int i = 0; i < 4; i++) {
        #pragma unroll
        for (int j = 0; j < 2; j++) {
            wmma::store_matrix_sync(eb, acc[i][j], 16, wmma::mem_row_major);
            __syncwarp();
            #pragma unroll
            for (int e = lane; e < 256; e += 32) {
                int r = e >> 4, c = e & 15;
                int gr = bm + wm + i * 16 + r;
                int gc = bn + wn + j * 16 + c;
                if (gc < N) {
                    float v = eb[e] + bias[gc];
                    if (EPI == EPI_RES)  v += extra[(size_t)gr * ldc + gc];
                    if (EPI == EPI_SILU) v = fsilu(v);
                    if (EPI == EPI_MUL)  v *= extra[(size_t)gr * ldc + gc];
                    C[(size_t)gr * ldc + gc] = v;
                }
            }
            __syncwarp();
        }
    }
}

// ---------------- Flash attention: PTX mma, regs-resident O, fast exp2 ------
// 256 threads (8 warps x 16 q-rows), Q-tile 128, KV-tile 64, double-buffered.
#define AKLD 68
#define AVLD 72
#define ASLD 68
#define AK_SZ (64 * AKLD)
#define AV_SZ (64 * AVLD)
#define AS_SZ (128 * ASLD)
#define ASMEM ((2 * AK_SZ + 2 * AV_SZ + AS_SZ) * 4)

__global__ void __launch_bounds__(256) attn_kernel(
    const float* __restrict__ qkv, float* __restrict__ out)
{
    extern __shared__ __align__(16) float sm[];
    float* Ks = sm;
    float* Vs = sm + 2 * AK_SZ;
    float* Ss = sm + 2 * AK_SZ + 2 * AV_SZ;
    uint32_t sK = (uint32_t)__cvta_generic_to_shared(Ks);
    uint32_t sV = (uint32_t)__cvta_generic_to_shared(Vs);

    int tid = threadIdx.x, lane = tid & 31, warp = tid >> 5;
    int gid = lane >> 2, tig = lane & 3;
    int qt = 15 - blockIdx.x;           // heavy tiles first
    int h  = blockIdx.y, bb = blockIdx.z;
    int q0 = qt * 128;
    int R  = warp * 16;
    const float LOG2E = 1.4426950408889634f;
    float qscale = 0.125f * LOG2E;
    float slope  = exp2f(-0.5f * (float)(h + 1)) * LOG2E;
    size_t base = (size_t)bb * TS * 3072;
    const float* Qg = qkv + base + h * 64;
    const float* Kg = Qg + 1024;
    const float* Vg = Qg + 2048;

    int nkb = 2 * qt + 2;

    auto loadKV = [&](int kb) {
        int stg = kb & 1, k0 = kb * 64;
        #pragma unroll
        for (int j = 0; j < 4; j++) {
            int idx = tid + j * 256;
            int r = idx >> 4, c4 = (idx & 15) << 2;
            size_t go = (size_t)(k0 + r) * 3072 + c4;
            cp16(sK + (uint32_t)(stg * AK_SZ + r * AKLD + c4) * 4u, Kg + go);
            cp16(sV + (uint32_t)(stg * AV_SZ + r * AVLD + c4) * 4u, Vg + go);
        }
    };

    loadKV(0);
    CP_COMMIT();

    // Q fragments in registers (rows R+gid, R+gid+8)
    uint32_t qa[8][4];
    {
        const float* Qr1 = Qg + (size_t)(q0 + R + gid) * 3072;
        const float* Qr2 = Qr1 + 8 * 3072;
        #pragma unroll
        for (int kt = 0; kt < 8; kt++) {
            int d0 = kt * 8 + tig;
            qa[kt][0] = f2tf32(Qr1[d0]     * qscale);
            qa[kt][1] = f2tf32(Qr2[d0]     * qscale);
            qa[kt][2] = f2tf32(Qr1[d0 + 4] * qscale);
            qa[kt][3] = f2tf32(Qr2[d0 + 4] * qscale);
        }
    }

    float oa[8][4];
    #pragma unroll
    for (int nt = 0; nt < 8; nt++)
        #pragma unroll
        for (int e = 0; e < 4; e++) oa[nt][e] = 0.0f;
    float m1 = -1e30f, m2 = -1e30f, l1 = 0.0f, l2 = 0.0f;

    int qp1 = q0 + R + gid, qp2 = qp1 + 8;
    float* Sw = Ss + R * ASLD;

    for (int kb = 0; kb < nkb; kb++) {
        if (kb + 1 < nkb) loadKV(kb + 1);
        CP_COMMIT();
        CP_WAIT1();
        __syncthreads();
        int k0 = kb * 64;
        const float* K = Ks + (kb & 1) * AK_SZ;
        const float* V = Vs + (kb & 1) * AV_SZ;

        if (k0 <= q0 + R + 15) {   // warp has at least one visible token
            // S = Q K^T
            float sacc[8][4];
            #pragma unroll
            for (int nt = 0; nt < 8; nt++)
                #pragma unroll
                for (int e = 0; e < 4; e++) sacc[nt][e] = 0.0f;
            #pragma unroll
            for (int kt = 0; kt < 8; kt++) {
                #pragma unroll
                for (int nt = 0; nt < 8; nt++) {
                    const float* kp = &K[(nt * 8 + gid) * AKLD + kt * 8 + tig];
                    uint32_t b0 = __float_as_uint(kp[0]);
                    uint32_t b1 = __float_as_uint(kp[4]);
                    mma8(sacc[nt], qa[kt], b0, b1);
                }
            }
            // bias + mask + row max
            bool domask = (k0 + 63 > q0 + R);
            float mx1 = -1e30f, mx2 = -1e30f;
            #pragma unroll
            for (int nt = 0; nt < 8; nt++) {
                int kp0 = k0 + nt * 8 + tig * 2;
                float s0 = sacc[nt][0] + slope * (float)(qp1 - kp0);
                float s1 = sacc[nt][1] + slope * (float)(qp1 - kp0 - 1);
                float s2 = sacc[nt][2] + slope * (float)(qp2 - kp0);
                float s3 = sacc[nt][3] + slope * (float)(qp2 - kp0 - 1);
                if (domask) {
                    if (kp0     > qp1) s0 = -1e30f;
                    if (kp0 + 1 > qp1) s1 = -1e30f;
                    if (kp0     > qp2) s2 = -1e30f;
                    if (kp0 + 1 > qp2) s3 = -1e30f;
                }
                sacc[nt][0] = s0; sacc[nt][1] = s1; sacc[nt][2] = s2; sacc[nt][3] = s3;
                mx1 = fmaxf(mx1, fmaxf(s0, s1));
                mx2 = fmaxf(mx2, fmaxf(s2, s3));
            }
            mx1 = fmaxf(mx1, __shfl_xor_sync(0xffffffffu, mx1, 1));
            mx1 = fmaxf(mx1, __shfl_xor_sync(0xffffffffu, mx1, 2));
            mx2 = fmaxf(mx2, __shfl_xor_sync(0xffffffffu, mx2, 1));
            mx2 = fmaxf(mx2, __shfl_xor_sync(0xffffffffu, mx2, 2));
            float mn1 = fmaxf(m1, mx1), mn2 = fmaxf(m2, mx2);
            float f1 = fexp2(m1 - mn1), f2 = fexp2(m2 - mn2);
            float sum1 = 0.0f, sum2 = 0.0f;
            #pragma unroll
            for (int nt = 0; nt < 8; nt++) {
                float p0 = fexp2(sacc[nt][0] - mn1);
                float p1 = fexp2(sacc[nt][1] - mn1);
                float p2 = fexp2(sacc[nt][2] - mn2);
                float p3 = fexp2(sacc[nt][3] - mn2);
                sum1 += p0 + p1; sum2 += p2 + p3;
                *(float2*)&Sw[gid * ASLD + nt * 8 + tig * 2]       = make_float2(p0, p1);
                *(float2*)&Sw[(gid + 8) * ASLD + nt * 8 + tig * 2] = make_float2(p2, p3);
            }
            sum1 += __shfl_xor_sync(0xffffffffu, sum1, 1);
            sum1 += __shfl_xor_sync(0xffffffffu, sum1, 2);
            sum2 += __shfl_xor_sync(0xffffffffu, sum2, 1);
            sum2 += __shfl_xor_sync(0xffffffffu, sum2, 2);
            l1 = l1 * f1 + sum1;  l2 = l2 * f2 + sum2;
            m1 = mn1;  m2 = mn2;
            // rescale O in registers
            #pragma unroll
            for (int nt = 0; nt < 8; nt++) {
                oa[nt][0] *= f1; oa[nt][1] *= f1;
                oa[nt][2] *= f2; oa[nt][3] *= f2;
            }
            __syncwarp();
            // O += P V
            #pragma unroll
            for (int kt = 0; kt < 8; kt++) {
                uint32_t pa[4];
                pa[0] = __float_as_uint(Sw[gid * ASLD + kt * 8 + tig]);
                pa[1] = __float_as_uint(Sw[(gid + 8) * ASLD + kt * 8 + tig]);
                pa[2] = __float_as_uint(Sw[gid * ASLD + kt * 8 + tig + 4]);
                pa[3] = __float_as_uint(Sw[(gid + 8) * ASLD + kt * 8 + tig + 4]);
                #pragma unroll
                for (int nt = 0; nt < 8; nt++) {
                    uint32_t b0 = __float_as_uint(V[(kt * 8 + tig) * AVLD + nt * 8 + gid]);
                    uint32_t b1 = __float_as_uint(V[(kt * 8 + tig + 4) * AVLD + nt * 8 + gid]);
                    mma8(oa[nt], pa, b0, b1);
                }
            }
        }
        __syncthreads();
    }

    float il1 = 1.0f / l1, il2 = 1.0f / l2;
    float* Or1 = out + (size_t)(bb * TS + q0 + R + gid) * N_EMBD + h * 64;
    float* Or2 = Or1 + 8 * N_EMBD;
    #pragma unroll
    for (int nt = 0; nt < 8; nt++) {
        *(float2*)&Or1[nt * 8 + tig * 2] = make_float2(oa[nt][0] * il1, oa[nt][1] * il1);
        *(float2*)&Or2[nt * 8 + tig * 2] = make_float2(oa[nt][2] * il2, oa[nt][3] * il2);
    }
}

// ---------------- launch -----------------------------------------------------
extern "C" void kernel_launch(void* const* d_in, const int* in_sizes, int n_in,
                              void* d_out, int out_size)
{
    (void)in_sizes; (void)n_in; (void)out_size;
    const float* x      = (const float*)d_in[0];
    const float* ln1_g  = (const float*)d_in[1];
    const float* ln1_b  = (const float*)d_in[2];
    const float* qkv_w  = (const float*)d_in[3];
    const float* qkv_b  = (const float*)d_in[4];
    const float* proj_w = (const float*)d_in[5];
    const float* proj_b = (const float*)d_in[6];
    const float* ln2_g  = (const float*)d_in[7];
    const float* ln2_b  = (const float*)d_in[8];
    const float* gate_w = (const float*)d_in[9];
    const float* gate_b = (const float*)d_in[10];
    const float* up_w   = (const float*)d_in[11];
    const float* up_b   = (const float*)d_in[12];
    const float* down_w = (const float*)d_in[13];
    const float* down_b = (const float*)d_in[14];
    float* out = (float*)d_out;

    float *h, *qkv, *att, *x2, *gate, *ff;
    cudaGetSymbolAddress((void**)&h,    g_h);
    cudaGetSymbolAddress((void**)&qkv,  g_qkv);
    cudaGetSymbolAddress((void**)&att,  g_att);
    cudaGetSymbolAddress((void**)&x2,   g_x2);
    cudaGetSymbolAddress((void**)&gate, g_gate);
    cudaGetSymbolAddress((void**)&ff,   g_ff);

    cudaFuncSetAttribute(gemm_tf32<EPI_BIAS, 4>, cudaFuncAttributeMaxDynamicSharedMemorySize, GSMEM);
    cudaFuncSetAttribute(gemm_tf32<EPI_RES,  4>, cudaFuncAttributeMaxDynamicSharedMemorySize, GSMEM);
    cudaFuncSetAttribute(gemm_tf32<EPI_SILU, 2>, cudaFuncAttributeMaxDynamicSharedMemorySize, GSMEM);
    cudaFuncSetAttribute(gemm_tf32<EPI_MUL,  2>, cudaFuncAttributeMaxDynamicSharedMemorySize, GSMEM);
    cudaFuncSetAttribute(attn_kernel, cudaFuncAttributeMaxDynamicSharedMemorySize, ASMEM);

    // 1) LN1
    ln_kernel<<<BT, 256>>>(x, ln1_g, ln1_b, h);
    // 2) qkv = h @ qkv_w + b
    {
        dim3 g(3 * N_EMBD / 128, BT / 128);
        gemm_tf32<EPI_BIAS, 4><<<g, 256, GSMEM>>>(h, qkv_w, qkv_b, nullptr, qkv,
                                                  BT, 3 * N_EMBD, N_EMBD, N_EMBD, 3 * N_EMBD);
    }
    // 3) attention
    {
        dim3 g(TS / 128, NHEAD, 2);
        attn_kernel<<<g, 256, ASMEM>>>(qkv, att);
    }
    // 4) x2 = att @ proj_w + b + x
    {
        dim3 g(N_EMBD / 128, BT / 128);
        gemm_tf32<EPI_RES, 4><<<g, 256, GSMEM>>>(att, proj_w, proj_b, x, x2,
                                                 BT, N_EMBD, N_EMBD, N_EMBD, N_EMBD);
    }
    // 5) LN2
    ln_kernel<<<BT, 256>>>(x2, ln2_g, ln2_b, h);
    // 6) gate = silu(h @ gate_w + b)   (ldc = FF_LD)
    {
        dim3 g((HID + 127) / 128, BT / 128);
        gemm_tf32<EPI_SILU, 2><<<g, 256, GSMEM>>>(h, gate_w, gate_b, nullptr, gate,
                                                  BT, HID, N_EMBD, N_EMBD, FF_LD);
        // 7) ff = (h @ up_w + b) * gate
        gemm_tf32<EPI_MUL, 2><<<g, 256, GSMEM>>>(h, up_w, up_b, gate, ff,
                                                 BT, HID, N_EMBD, N_EMBD, FF_LD);
    }
    // 8) out = ff @ down_w + b + x2   (lda = FF_LD; ff pad cols are zero)
    {
        dim3 g(N_EMBD / 128, BT / 128);
        gemm_tf32<EPI_RES, 4><<<g, 256, GSMEM>>>(ff, down_w, down_b, x2, out,
                                                 BT, N_EMBD, HID, FF_LD, N_EMBD);
    }
}

// round 3
// speedup vs baseline: 1.7748x; 1.1010x over previous
#include <cuda_runtime.h>
#include <mma.h>
#include <math.h>
#include <stdint.h>

using namespace nvcuda;

#define N_EMBD 1024
#define NHEAD  16
#define HID    2730
#define FF_LD  2752   // padded stride for gate/ff scratch
#define WP_LD  2816   // padded stride for gate_w/up_w scratch (22*128)
#define BT     4096
#define TS     2048
#define LN_EPS 1e-5f

// ---------------- scratch ---------------------------------------------------
__device__ float g_h   [(size_t)BT * N_EMBD];
__device__ float g_qkv [(size_t)BT * 3 * N_EMBD];
__device__ float g_att [(size_t)BT * N_EMBD];
__device__ float g_x2  [(size_t)BT * N_EMBD];
__device__ float g_gate[(size_t)BT * FF_LD];   // pad cols stay zero (BSS, never written)
__device__ float g_ff  [(size_t)BT * FF_LD];
__device__ float g_wg  [(size_t)N_EMBD * WP_LD];
__device__ float g_wu  [(size_t)N_EMBD * WP_LD];

// ---------------- helpers ----------------------------------------------------
__device__ __forceinline__ void cp16(uint32_t dst, const void* src) {
    asm volatile("cp.async.cg.shared.global [%0], [%1], 16;\n" :: "r"(dst), "l"(src));
}
__device__ __forceinline__ void cp16p(uint32_t dst, const void* src, int pb) {
    asm volatile("cp.async.cg.shared.global [%0], [%1], 16, %2;\n" :: "r"(dst), "l"(src), "r"(pb));
}
#define CP_COMMIT() asm volatile("cp.async.commit_group;\n")
#define CP_WAIT1()  asm volatile("cp.async.wait_group 1;\n")

// fast 2^t for t <= 0 (FMA-only)
__device__ __forceinline__ float fexp2(float t) {
    t = fmaxf(t, -126.0f);
    float r = t + 12582912.0f;
    int   fi = __float_as_int(r) - 0x4B400000;
    float f = t - (r - 12582912.0f);
    float p = 1.3333558e-3f;
    p = fmaf(p, f, 9.6181291e-3f);
    p = fmaf(p, f, 5.5504109e-2f);
    p = fmaf(p, f, 2.4022651e-1f);
    p = fmaf(p, f, 6.9314718e-1f);
    p = fmaf(p, f, 1.0f);
    return __int_as_float(__float_as_int(p) + (fi << 23));
}
__device__ __forceinline__ float fsilu(float v) {
    float e = fexp2(-fabsf(v) * 1.4426950408889634f);
    float d = 1.0f + e;
    float y = 1.4571429f - 0.45714286f * d;
    y = y * (2.0f - d * y);
    y = y * (2.0f - d * y);
    float sig = (v >= 0.0f) ? y : (1.0f - y);
    return v * sig;
}

__device__ __forceinline__ void mma8(float* c, const uint32_t* a, uint32_t b0, uint32_t b1) {
    asm volatile(
        "mma.sync.aligned.m16n8k8.row.col.f32.tf32.tf32.f32 "
        "{%0,%1,%2,%3}, {%4,%5,%6,%7}, {%8,%9}, {%0,%1,%2,%3};\n"
        : "+f"(c[0]), "+f"(c[1]), "+f"(c[2]), "+f"(c[3])
        : "r"(a[0]), "r"(a[1]), "r"(a[2]), "r"(a[3]), "r"(b0), "r"(b1));
}
__device__ __forceinline__ uint32_t f2tf32(float x) {
    uint32_t u; asm("cvt.rna.tf32.f32 %0, %1;" : "=r"(u) : "f"(x)); return u;
}

// ---------------- weight pad kernel -----------------------------------------
__global__ void __launch_bounds__(256) pad_w_kernel(
    const float* __restrict__ w, float* __restrict__ out)
{
    int idx = blockIdx.x * 256 + threadIdx.x;
    if (idx >= N_EMBD * WP_LD) return;
    int row = idx / WP_LD, col = idx - row * WP_LD;
    out[idx] = (col < HID) ? w[(size_t)row * HID + col] : 0.0f;
}

// ---------------- LayerNorm --------------------------------------------------
__global__ void __launch_bounds__(256) ln_kernel(
    const float* __restrict__ x, const float* __restrict__ g,
    const float* __restrict__ b, float* __restrict__ out)
{
    int row = blockIdx.x;
    int tid = threadIdx.x;
    const float4* xr = (const float4*)(x + (size_t)row * N_EMBD);
    float4 v = xr[tid];
    float s  = v.x + v.y + v.z + v.w;
    float ss = v.x*v.x + v.y*v.y + v.z*v.z + v.w*v.w;
    #pragma unroll
    for (int o = 16; o; o >>= 1) {
        s  += __shfl_xor_sync(0xffffffffu, s, o);
        ss += __shfl_xor_sync(0xffffffffu, ss, o);
    }
    __shared__ float red[16];
    int warp = tid >> 5, lane = tid & 31;
    if (lane == 0) { red[warp] = s; red[8 + warp] = ss; }
    __syncthreads();
    if (tid == 0) {
        float a = 0.f, a2 = 0.f;
        #pragma unroll
        for (int i = 0; i < 8; i++) { a += red[i]; a2 += red[8 + i]; }
        red[0] = a; red[8] = a2;
    }
    __syncthreads();
    float mean = red[0] * (1.0f / N_EMBD);
    float var  = red[8] * (1.0f / N_EMBD) - mean * mean;
    float rstd = rsqrtf(var + LN_EPS);
    float4 go = ((const float4*)g)[tid];
    float4 bo = ((const float4*)b)[tid];
    float4 o;
    o.x = (v.x - mean) * rstd * go.x + bo.x;
    o.y = (v.y - mean) * rstd * go.y + bo.y;
    o.z = (v.z - mean) * rstd * go.z + bo.z;
    o.w = (v.w - mean) * rstd * go.w + bo.w;
    ((float4*)(out + (size_t)row * N_EMBD))[tid] = o;
}

// ---------------- TF32 WMMA GEMM, BK=32, double buffered, no cvt ------------
#define GA_ST 4608
#define GB_ST 4352
#define GSMEM ((2*GA_ST + 2*GB_ST) * 4)

enum { EPI_BIAS = 0, EPI_RES = 1, EPI_SILU = 2, EPI_MUL = 3 };

template <int EPI>
__global__ void __launch_bounds__(256, 2) gemm_tf32(
    const float* __restrict__ A, const float* __restrict__ B,
    const float* __restrict__ bias, const float* __restrict__ extra,
    float* __restrict__ C, int N, int K, int lda, int ldb, int ldc)
{
    extern __shared__ __align__(16) float sm[];
    float* As = sm;
    float* Bs = sm + 2 * GA_ST;
    uint32_t sA = (uint32_t)__cvta_generic_to_shared(As);
    uint32_t sB = (uint32_t)__cvta_generic_to_shared(Bs);

    int tid = threadIdx.x;
    int warp = tid >> 5, lane = tid & 31;
    int bm = blockIdx.y * 128, bn = blockIdx.x * 128;
    int wm = (warp >> 2) * 64, wn = (warp & 3) * 32;
    int nkt = (K + 31) >> 5;

    wmma::fragment<wmma::accumulator, 16, 16, 8, float> acc[4][2];
    #pragma unroll
    for (int i = 0; i < 4; i++)
        #pragma unroll
        for (int j = 0; j < 2; j++)
            wmma::fill_fragment(acc[i][j], 0.0f);

    auto loadT = [&](int kt) {
        int stg = kt & 1;
        int k0 = kt << 5;
        #pragma unroll
        for (int j = 0; j < 4; j++) {             // A: 128x32 (lda padded, in-bounds)
            int idx = tid + j * 256;
            int r = idx >> 3, c4 = (idx & 7) << 2;
            uint32_t dst = sA + (uint32_t)(stg * GA_ST + r * 36 + c4) * 4u;
            cp16(dst, A + (size_t)(bm + r) * lda + k0 + c4);
        }
        #pragma unroll
        for (int j = 0; j < 4; j++) {             // B: 32x128, 16B (ldb covers bn+127)
            int idx = tid + j * 256;
            int r = idx >> 5, c4 = (idx & 31) << 2;
            int kk = k0 + r;
            int pb = (kk < K) ? 16 : 0;
            uint32_t dst = sB + (uint32_t)(stg * GB_ST + r * 136 + c4) * 4u;
            cp16p(dst, B + (size_t)kk * ldb + bn + c4, pb);
        }
    };

    loadT(0);
    CP_COMMIT();
    for (int kt = 0; kt < nkt; kt++) {
        if (kt + 1 < nkt) loadT(kt + 1);
        CP_COMMIT();
        CP_WAIT1();
        __syncthreads();
        const float* Ab = As + (kt & 1) * GA_ST;
        const float* Bb = Bs + (kt & 1) * GB_ST;
        #pragma unroll
        for (int ks = 0; ks < 4; ks++) {
            wmma::fragment<wmma::matrix_a, 16, 16, 8, wmma::precision::tf32, wmma::row_major> a[4];
            wmma::fragment<wmma::matrix_b, 16, 16, 8, wmma::precision::tf32, wmma::row_major> bf[2];
            #pragma unroll
            for (int i = 0; i < 4; i++)
                wmma::load_matrix_sync(a[i], &Ab[(wm + i * 16) * 36 + ks * 8], 36);
            #pragma unroll
            for (int j = 0; j < 2; j++)
                wmma::load_matrix_sync(bf[j], &Bb[(ks * 8) * 136 + wn + j * 16], 136);
            #pragma unroll
            for (int i = 0; i < 4; i++)
                #pragma unroll
                for (int j = 0; j < 2; j++)
                    wmma::mma_sync(acc[i][j], a[i], bf[j], acc[i][j]);
        }
        __syncthreads();
    }

    float* eb = sm + warp * 256;
    #pragma unroll
    for (int i = 0; i < 4; i++) {
        #pragma unroll
        for (int j = 0; j < 2; j++) {
            wmma::store_matrix_sync(eb, acc[i][j], 16, wmma::mem_row_major);
            __syncwarp();
            #pragma unroll
            for (int e = lane; e < 256; e += 32) {
                int r = e >> 4, c = e & 15;
                int gr = bm + wm + i * 16 + r;
                int gc = bn + wn + j * 16 + c;
                if (gc < N) {
                    float v = eb[e] + bias[gc];
                    if (EPI == EPI_RES)  v += extra[(size_t)gr * ldc + gc];
                    if (EPI == EPI_SILU) v = fsilu(v);
                    if (EPI == EPI_MUL)  v *= extra[(size_t)gr * ldc + gc];
                    C[(size_t)gr * ldc + gc] = v;
                }
            }
            __syncwarp();
        }
    }
}

// ---------------- Flash attention --------------------------------------------
#define AKLD 68
#define AVLD 72
#define ASLD 68
#define AK_SZ (64 * AKLD)
#define AV_SZ (64 * AVLD)
#define AS_SZ (128 * ASLD)
#define ASMEM ((2 * AK_SZ + 2 * AV_SZ + AS_SZ) * 4)

__global__ void __launch_bounds__(256) attn_kernel(
    const float* __restrict__ qkv, float* __restrict__ out)
{
    extern __shared__ __align__(16) float sm[];
    float* Ks = sm;
    float* Vs = sm + 2 * AK_SZ;
    float* Ss = sm + 2 * AK_SZ + 2 * AV_SZ;
    uint32_t sK = (uint32_t)__cvta_generic_to_shared(Ks);
    uint32_t sV = (uint32_t)__cvta_generic_to_shared(Vs);

    int tid = threadIdx.x, lane = tid & 31, warp = tid >> 5;
    int gid = lane >> 2, tig = lane & 3;
    int qt = 15 - blockIdx.x;
    int h  = blockIdx.y, bb = blockIdx.z;
    int q0 = qt * 128;
    int R  = warp * 16;
    const float LOG2E = 1.4426950408889634f;
    float qscale = 0.125f * LOG2E;
    float slope  = exp2f(-0.5f * (float)(h + 1)) * LOG2E;
    size_t base = (size_t)bb * TS * 3072;
    const float* Qg = qkv + base + h * 64;
    const float* Kg = Qg + 1024;
    const float* Vg = Qg + 2048;

    int nkb = 2 * qt + 2;

    auto loadKV = [&](int kb) {
        int stg = kb & 1, k0 = kb * 64;
        #pragma unroll
        for (int j = 0; j < 4; j++) {
            int idx = tid + j * 256;
            int r = idx >> 4, c4 = (idx & 15) << 2;
            size_t go = (size_t)(k0 + r) * 3072 + c4;
            cp16(sK + (uint32_t)(stg * AK_SZ + r * AKLD + c4) * 4u, Kg + go);
            cp16(sV + (uint32_t)(stg * AV_SZ + r * AVLD + c4) * 4u, Vg + go);
        }
    };

    loadKV(0);
    CP_COMMIT();

    uint32_t qa[8][4];
    {
        const float* Qr1 = Qg + (size_t)(q0 + R + gid) * 3072;
        const float* Qr2 = Qr1 + 8 * 3072;
        #pragma unroll
        for (int kt = 0; kt < 8; kt++) {
            int d0 = kt * 8 + tig;
            qa[kt][0] = f2tf32(Qr1[d0]     * qscale);
            qa[kt][1] = f2tf32(Qr2[d0]     * qscale);
            qa[kt][2] = f2tf32(Qr1[d0 + 4] * qscale);
            qa[kt][3] = f2tf32(Qr2[d0 + 4] * qscale);
        }
    }

    float oa[8][4];
    #pragma unroll
    for (int nt = 0; nt < 8; nt++)
        #pragma unroll
        for (int e = 0; e < 4; e++) oa[nt][e] = 0.0f;
    float m1 = -1e30f, m2 = -1e30f, l1 = 0.0f, l2 = 0.0f;

    int qp1 = q0 + R + gid, qp2 = qp1 + 8;
    float* Sw = Ss + R * ASLD;

    for (int kb = 0; kb < nkb; kb++) {
        if (kb + 1 < nkb) loadKV(kb + 1);
        CP_COMMIT();
        CP_WAIT1();
        __syncthreads();
        int k0 = kb * 64;
        const float* K = Ks + (kb & 1) * AK_SZ;
        const float* V = Vs + (kb & 1) * AV_SZ;
        int vis = q0 + R + 15 - k0;           // last visible col offset for this warp

        if (vis >= 0) {
            int ntmax = vis >> 3;              // tiles 0..ntmax have >=1 visible col
            ntmax = (ntmax >= 7) ? 8 : (ntmax + 1);
            float sacc[8][4];
            #pragma unroll
            for (int nt = 0; nt < 8; nt++)
                #pragma unroll
                for (int e = 0; e < 4; e++) sacc[nt][e] = 0.0f;
            #pragma unroll
            for (int kt = 0; kt < 8; kt++) {
                #pragma unroll
                for (int nt = 0; nt < 8; nt++) {
                    if (nt < ntmax) {
                        const float* kp = &K[(nt * 8 + gid) * AKLD + kt * 8 + tig];
                        uint32_t b0 = __float_as_uint(kp[0]);
                        uint32_t b1 = __float_as_uint(kp[4]);
                        mma8(sacc[nt], qa[kt], b0, b1);
                    }
                }
            }
            bool domask = (k0 + 63 > q0 + R);
            float mx1 = -1e30f, mx2 = -1e30f;
            #pragma unroll
            for (int nt = 0; nt < 8; nt++) {
                if (nt >= ntmax) continue;
                int kp0 = k0 + nt * 8 + tig * 2;
                float s0 = sacc[nt][0] + slope * (float)(qp1 - kp0);
                float s1 = sacc[nt][1] + slope * (float)(qp1 - kp0 - 1);
                float s2 = sacc[nt][2] + slope * (float)(qp2 - kp0);
                float s3 = sacc[nt][3] + slope * (float)(qp2 - kp0 - 1);
                if (domask) {
                    if (kp0     > qp1) s0 = -1e30f;
                    if (kp0 + 1 > qp1) s1 = -1e30f;
                    if (kp0     > qp2) s2 = -1e30f;
                    if (kp0 + 1 > qp2) s3 = -1e30f;
                }
                sacc[nt][0] = s0; sacc[nt][1] = s1; sacc[nt][2] = s2; sacc[nt][3] = s3;
                mx1 = fmaxf(mx1, fmaxf(s0, s1));
                mx2 = fmaxf(mx2, fmaxf(s2, s3));
            }
            mx1 = fmaxf(mx1, __shfl_xor_sync(0xffffffffu, mx1, 1));
            mx1 = fmaxf(mx1, __shfl_xor_sync(0xffffffffu, mx1, 2));
            mx2 = fmaxf(mx2, __shfl_xor_sync(0xffffffffu, mx2, 1));
            mx2 = fmaxf(mx2, __shfl_xor_sync(0xffffffffu, mx2, 2));
            float mn1 = fmaxf(m1, mx1), mn2 = fmaxf(m2, mx2);
            float f1 = fexp2(m1 - mn1), f2 = fexp2(m2 - mn2);
            float sum1 = 0.0f, sum2 = 0.0f;
            #pragma unroll
            for (int nt = 0; nt < 8; nt++) {
                if (nt >= ntmax) continue;
                float p0 = fexp2(sacc[nt][0] - mn1);
                float p1 = fexp2(sacc[nt][1] - mn1);
                float p2 = fexp2(sacc[nt][2] - mn2);
                float p3 = fexp2(sacc[nt][3] - mn2);
                sum1 += p0 + p1; sum2 += p2 + p3;
                *(float2*)&Sw[gid * ASLD + nt * 8 + tig * 2]       = make_float2(p0, p1);
                *(float2*)&Sw[(gid + 8) * ASLD + nt * 8 + tig * 2] = make_float2(p2, p3);
            }
            sum1 += __shfl_xor_sync(0xffffffffu, sum1, 1);
            sum1 += __shfl_xor_sync(0xffffffffu, sum1, 2);
            sum2 += __shfl_xor_sync(0xffffffffu, sum2, 1);
            sum2 += __shfl_xor_sync(0xffffffffu, sum2, 2);
            l1 = l1 * f1 + sum1;  l2 = l2 * f2 + sum2;
            m1 = mn1;  m2 = mn2;
            #pragma unroll
            for (int nt = 0; nt < 8; nt++) {
                oa[nt][0] *= f1; oa[nt][1] *= f1;
                oa[nt][2] *= f2; oa[nt][3] *= f2;
            }
            __syncwarp();
            #pragma unroll
            for (int kt = 0; kt < 8; kt++) {
                if (kt >= ntmax) continue;        // keys beyond diag have p=0
                uint32_t pa[4];
                pa[0] = __float_as_uint(Sw[gid * ASLD + kt * 8 + tig]);
                pa[1] = __float_as_uint(Sw[(gid + 8) * ASLD + kt * 8 + tig]);
                pa[2] = __float_as_uint(Sw[gid * ASLD + kt * 8 + tig + 4]);
                pa[3] = __float_as_uint(Sw[(gid + 8) * ASLD + kt * 8 + tig + 4]);
                #pragma unroll
                for (int nt = 0; nt < 8; nt++) {
                    uint32_t b0 = __float_as_uint(V[(kt * 8 + tig) * AVLD + nt * 8 + gid]);
                    uint32_t b1 = __float_as_uint(V[(kt * 8 + tig + 4) * AVLD + nt * 8 + gid]);
                    mma8(oa[nt], pa, b0, b1);
                }
            }
        }
        __syncthreads();
    }

    float il1 = 1.0f / l1, il2 = 1.0f / l2;
    float* Or1 = out + (size_t)(bb * TS + q0 + R + gid) * N_EMBD + h * 64;
    float* Or2 = Or1 + 8 * N_EMBD;
    #pragma unroll
    for (int nt = 0; nt < 8; nt++) {
        *(float2*)&Or1[nt * 8 + tig * 2] = make_float2(oa[nt][0] * il1, oa[nt][1] * il1);
        *(float2*)&Or2[nt * 8 + tig * 2] = make_float2(oa[nt][2] * il2, oa[nt][3] * il2);
    }
}

// ---------------- launch -----------------------------------------------------
extern "C" void kernel_launch(void* const* d_in, const int* in_sizes, int n_in,
                              void* d_out, int out_size)
{
    (void)in_sizes; (void)n_in; (void)out_size;
    const float* x      = (const float*)d_in[0];
    const float* ln1_g  = (const float*)d_in[1];
    const float* ln1_b  = (const float*)d_in[2];
    const float* qkv_w  = (const float*)d_in[3];
    const float* qkv_b  = (const float*)d_in[4];
    const float* proj_w = (const float*)d_in[5];
    const float* proj_b = (const float*)d_in[6];
    const float* ln2_g  = (const float*)d_in[7];
    const float* ln2_b  = (const float*)d_in[8];
    const float* gate_w = (const float*)d_in[9];
    const float* gate_b = (const float*)d_in[10];
    const float* up_w   = (const float*)d_in[11];
    const float* up_b   = (const float*)d_in[12];
    const float* down_w = (const float*)d_in[13];
    const float* down_b = (const float*)d_in[14];
    float* out = (float*)d_out;

    float *h, *qkv, *att, *x2, *gate, *ff, *wg, *wu;
    cudaGetSymbolAddress((void**)&h,    g_h);
    cudaGetSymbolAddress((void**)&qkv,  g_qkv);
    cudaGetSymbolAddress((void**)&att,  g_att);
    cudaGetSymbolAddress((void**)&x2,   g_x2);
    cudaGetSymbolAddress((void**)&gate, g_gate);
    cudaGetSymbolAddress((void**)&ff,   g_ff);
    cudaGetSymbolAddress((void**)&wg,   g_wg);
    cudaGetSymbolAddress((void**)&wu,   g_wu);

    cudaFuncSetAttribute(gemm_tf32<EPI_BIAS>, cudaFuncAttributeMaxDynamicSharedMemorySize, GSMEM);
    cudaFuncSetAttribute(gemm_tf32<EPI_RES >, cudaFuncAttributeMaxDynamicSharedMemorySize, GSMEM);
    cudaFuncSetAttribute(gemm_tf32<EPI_SILU>, cudaFuncAttributeMaxDynamicSharedMemorySize, GSMEM);
    cudaFuncSetAttribute(gemm_tf32<EPI_MUL >, cudaFuncAttributeMaxDynamicSharedMemorySize, GSMEM);
    cudaFuncSetAttribute(attn_kernel, cudaFuncAttributeMaxDynamicSharedMemorySize, ASMEM);

    // 0) pad gate/up weights into 2816-stride scratch (enables 16B path)
    {
        int n = N_EMBD * WP_LD;
        pad_w_kernel<<<(n + 255) / 256, 256>>>(gate_w, wg);
        pad_w_kernel<<<(n + 255) / 256, 256>>>(up_w, wu);
    }
    // 1) LN1
    ln_kernel<<<BT, 256>>>(x, ln1_g, ln1_b, h);
    // 2) qkv = h @ qkv_w + b
    {
        dim3 g(3 * N_EMBD / 128, BT / 128);
        gemm_tf32<EPI_BIAS><<<g, 256, GSMEM>>>(h, qkv_w, qkv_b, nullptr, qkv,
                                               3 * N_EMBD, N_EMBD, N_EMBD, 3 * N_EMBD, 3 * N_EMBD);
    }
    // 3) attention
    {
        dim3 g(TS / 128, NHEAD, 2);
        attn_kernel<<<g, 256, ASMEM>>>(qkv, att);
    }
    // 4) x2 = att @ proj_w + b + x
    {
        dim3 g(N_EMBD / 128, BT / 128);
        gemm_tf32<EPI_RES><<<g, 256, GSMEM>>>(att, proj_w, proj_b, x, x2,
                                              N_EMBD, N_EMBD, N_EMBD, N_EMBD, N_EMBD);
    }
    // 5) LN2
    ln_kernel<<<BT, 256>>>(x2, ln2_g, ln2_b, h);
    // 6) gate = silu(h @ wg + b)
    {
        dim3 g(WP_LD / 128, BT / 128);
        gemm_tf32<EPI_SILU><<<g, 256, GSMEM>>>(h, wg, gate_b, nullptr, gate,
                                               HID, N_EMBD, N_EMBD, WP_LD, FF_LD);
        // 7) ff = (h @ wu + b) * gate
        gemm_tf32<EPI_MUL><<<g, 256, GSMEM>>>(h, wu, up_b, gate, ff,
                                              HID, N_EMBD, N_EMBD, WP_LD, FF_LD);
    }
    // 8) out = ff @ down_w + b + x2
    {
        dim3 g(N_EMBD / 128, BT / 128);
        gemm_tf32<EPI_RES><<<g, 256, GSMEM>>>(ff, down_w, down_b, x2, out,
                                              N_EMBD, HID, FF_LD, N_EMBD, N_EMBD);
    }
}

// round 5
// speedup vs baseline: 5.3982x; 3.0416x over previous
#include <cuda_runtime.h>
#include <cuda_fp16.h>
#include <mma.h>
#include <math.h>
#include <stdint.h>

using namespace nvcuda;

#define N_EMBD 1024
#define NHEAD  16
#define HID    2730
#define FF_LD  2752
#define WP_LD  2816
#define BT     4096
#define TS     2048
#define LN_EPS 1e-5f

// ---------------- scratch ---------------------------------------------------
__device__ __half g_hh  [(size_t)BT * N_EMBD];
__device__ __half g_qkvh[(size_t)BT * 3 * N_EMBD];
__device__ __half g_atth[(size_t)BT * N_EMBD];
__device__ __half g_ffh [(size_t)BT * FF_LD];    // pad cols stay zero (BSS)
__device__ float  g_x2  [(size_t)BT * N_EMBD];
__device__ float  g_gate[(size_t)BT * FF_LD];
__device__ __half g_qkvw[(size_t)N_EMBD * 3 * N_EMBD];
__device__ __half g_projw[(size_t)N_EMBD * N_EMBD];
__device__ __half g_downw[(size_t)HID * N_EMBD];
__device__ __half g_wg  [(size_t)N_EMBD * WP_LD];
__device__ __half g_wu  [(size_t)N_EMBD * WP_LD];

// ---------------- helpers ----------------------------------------------------
__device__ __forceinline__ void cp16(uint32_t dst, const void* src) {
    asm volatile("cp.async.cg.shared.global [%0], [%1], 16;\n" :: "r"(dst), "l"(src));
}
__device__ __forceinline__ void cp16p(uint32_t dst, const void* src, int pb) {
    asm volatile("cp.async.cg.shared.global [%0], [%1], 16, %2;\n" :: "r"(dst), "l"(src), "r"(pb));
}
#define CP_COMMIT() asm volatile("cp.async.commit_group;\n")
#define CP_WAIT1()  asm volatile("cp.async.wait_group 1;\n")

__device__ __forceinline__ float fexp2(float t) {
    t = fmaxf(t, -126.0f);
    float r = t + 12582912.0f;
    int   fi = __float_as_int(r) - 0x4B400000;
    float f = t - (r - 12582912.0f);
    float p = 1.3333558e-3f;
    p = fmaf(p, f, 9.6181291e-3f);
    p = fmaf(p, f, 5.5504109e-2f);
    p = fmaf(p, f, 2.4022651e-1f);
    p = fmaf(p, f, 6.9314718e-1f);
    p = fmaf(p, f, 1.0f);
    return __int_as_float(__float_as_int(p) + (fi << 23));
}
__device__ __forceinline__ float fsilu(float v) {
    float e = fexp2(-fabsf(v) * 1.4426950408889634f);
    float d = 1.0f + e;
    float y = 1.4571429f - 0.45714286f * d;
    y = y * (2.0f - d * y);
    y = y * (2.0f - d * y);
    float sig = (v >= 0.0f) ? y : (1.0f - y);
    return v * sig;
}

__device__ __forceinline__ void mma16(float* c, const uint32_t* a, uint32_t b0, uint32_t b1) {
    asm volatile(
        "mma.sync.aligned.m16n8k16.row.col.f32.f16.f16.f32 "
        "{%0,%1,%2,%3}, {%4,%5,%6,%7}, {%8,%9}, {%0,%1,%2,%3};\n"
        : "+f"(c[0]), "+f"(c[1]), "+f"(c[2]), "+f"(c[3])
        : "r"(a[0]), "r"(a[1]), "r"(a[2]), "r"(a[3]), "r"(b0), "r"(b1));
}
__device__ __forceinline__ void ldsm_t2(uint32_t& r0, uint32_t& r1, uint32_t addr) {
    asm volatile("ldmatrix.sync.aligned.m8n8.x2.trans.shared.b16 {%0,%1}, [%2];"
        : "=r"(r0), "=r"(r1) : "r"(addr));
}
__device__ __forceinline__ uint32_t pkh2(float a, float b) {
    __half2 h = __floats2half2_rn(a, b);
    return *(uint32_t*)&h;
}

// ---------------- conversion kernels -----------------------------------------
__global__ void __launch_bounds__(256) conv_kernel(
    const float* __restrict__ w, __half* __restrict__ out, int n)
{
    int idx = blockIdx.x * 256 + threadIdx.x;
    if (idx < n) out[idx] = __float2half(w[idx]);
}
__global__ void __launch_bounds__(256) padconv_kernel(
    const float* __restrict__ w, __half* __restrict__ out)
{
    int idx = blockIdx.x * 256 + threadIdx.x;
    if (idx >= N_EMBD * WP_LD) return;
    int row = idx / WP_LD, col = idx - row * WP_LD;
    out[idx] = (col < HID) ? __float2half(w[(size_t)row * HID + col]) : __half(0.0f);
}

// ---------------- LayerNorm (fp32 in, half out) ------------------------------
__global__ void __launch_bounds__(256) ln_kernel(
    const float* __restrict__ x, const float* __restrict__ g,
    const float* __restrict__ b, __half* __restrict__ out)
{
    int row = blockIdx.x;
    int tid = threadIdx.x;
    const float4* xr = (const float4*)(x + (size_t)row * N_EMBD);
    float4 v = xr[tid];
    float s  = v.x + v.y + v.z + v.w;
    float ss = v.x*v.x + v.y*v.y + v.z*v.z + v.w*v.w;
    #pragma unroll
    for (int o = 16; o; o >>= 1) {
        s  += __shfl_xor_sync(0xffffffffu, s, o);
        ss += __shfl_xor_sync(0xffffffffu, ss, o);
    }
    __shared__ float red[16];
    int warp = tid >> 5, lane = tid & 31;
    if (lane == 0) { red[warp] = s; red[8 + warp] = ss; }
    __syncthreads();
    if (tid == 0) {
        float a = 0.f, a2 = 0.f;
        #pragma unroll
        for (int i = 0; i < 8; i++) { a += red[i]; a2 += red[8 + i]; }
        red[0] = a; red[8] = a2;
    }
    __syncthreads();
    float mean = red[0] * (1.0f / N_EMBD);
    float var  = red[8] * (1.0f / N_EMBD) - mean * mean;
    float rstd = rsqrtf(var + LN_EPS);
    float4 go = ((const float4*)g)[tid];
    float4 bo = ((const float4*)b)[tid];
    uint2 u;
    u.x = pkh2((v.x - mean) * rstd * go.x + bo.x, (v.y - mean) * rstd * go.y + bo.y);
    u.y = pkh2((v.z - mean) * rstd * go.z + bo.z, (v.w - mean) * rstd * go.w + bo.w);
    ((uint2*)(out + (size_t)row * N_EMBD))[tid] = u;
}

// ---------------- FP16 WMMA GEMM, BK=64, double buffered ---------------------
#define H_ALD 72
#define H_BLD 136
#define H_AST (128 * H_ALD)     // halves per A stage
#define H_BST (64 * H_BLD)      // halves per B stage
#define GSMEM ((2 * H_AST + 2 * H_BST) * 2)

enum { EPI_BIAS = 0, EPI_RES = 1, EPI_SILU = 2, EPI_MUL = 3 };

template <int EPI, int OH>
__global__ void __launch_bounds__(256, 2) gemm_fp16(
    const __half* __restrict__ A, const __half* __restrict__ B,
    const float* __restrict__ bias, const float* __restrict__ extra,
    void* __restrict__ Cv, int N, int K, int lda, int ldb, int ldc)
{
    extern __shared__ __align__(16) char smc[];
    __half* As = (__half*)smc;
    __half* Bs = As + 2 * H_AST;
    uint32_t sA = (uint32_t)__cvta_generic_to_shared(As);
    uint32_t sB = (uint32_t)__cvta_generic_to_shared(Bs);

    int tid = threadIdx.x;
    int warp = tid >> 5, lane = tid & 31;
    int bm = blockIdx.y * 128, bn = blockIdx.x * 128;
    int wm = (warp >> 2) * 64, wn = (warp & 3) * 32;
    int nkt = (K + 63) >> 6;

    wmma::fragment<wmma::accumulator, 16, 16, 16, float> acc[4][2];
    #pragma unroll
    for (int i = 0; i < 4; i++)
        #pragma unroll
        for (int j = 0; j < 2; j++)
            wmma::fill_fragment(acc[i][j], 0.0f);

    auto loadT = [&](int kt) {
        int stg = kt & 1;
        int k0 = kt << 6;
        #pragma unroll
        for (int j = 0; j < 4; j++) {             // A: 128 rows x 64 halves
            int idx = tid + j * 256;
            int r = idx >> 3, c8 = (idx & 7) << 3;
            uint32_t dst = sA + (uint32_t)(stg * H_AST + r * H_ALD + c8) * 2u;
            cp16(dst, A + (size_t)(bm + r) * lda + k0 + c8);
        }
        #pragma unroll
        for (int j = 0; j < 4; j++) {             // B: 64 rows x 128 halves
            int idx = tid + j * 256;
            int r = idx >> 4, c8 = (idx & 15) << 3;
            int kk = k0 + r;
            int pb = (kk < K) ? 16 : 0;
            uint32_t dst = sB + (uint32_t)(stg * H_BST + r * H_BLD + c8) * 2u;
            cp16p(dst, B + (size_t)kk * ldb + bn + c8, pb);
        }
    };

    loadT(0);
    CP_COMMIT();
    for (int kt = 0; kt < nkt; kt++) {
        if (kt + 1 < nkt) loadT(kt + 1);
        CP_COMMIT();
        CP_WAIT1();
        __syncthreads();
        const __half* Ab = As + (kt & 1) * H_AST;
        const __half* Bb = Bs + (kt & 1) * H_BST;
        #pragma unroll
        for (int ks = 0; ks < 4; ks++) {
            wmma::fragment<wmma::matrix_a, 16, 16, 16, __half, wmma::row_major> a[4];
            wmma::fragment<wmma::matrix_b, 16, 16, 16, __half, wmma::row_major> bf[2];
            #pragma unroll
            for (int i = 0; i < 4; i++)
                wmma::load_matrix_sync(a[i], &Ab[(wm + i * 16) * H_ALD + ks * 16], H_ALD);
            #pragma unroll
            for (int j = 0; j < 2; j++)
                wmma::load_matrix_sync(bf[j], &Bb[(ks * 16) * H_BLD + wn + j * 16], H_BLD);
            #pragma unroll
            for (int i = 0; i < 4; i++)
                #pragma unroll
                for (int j = 0; j < 2; j++)
                    wmma::mma_sync(acc[i][j], a[i], bf[j], acc[i][j]);
        }
        __syncthreads();
    }

    float* eb = (float*)smc + warp * 256;
    #pragma unroll
    for (int i = 0; i < 4; i++) {
        #pragma unroll
        for (int j = 0; j < 2; j++) {
            wmma::store_matrix_sync(eb, acc[i][j], 16, wmma::mem_row_major);
            __syncwarp();
            #pragma unroll
            for (int e = lane; e < 256; e += 32) {
                int r = e >> 4, c = e & 15;
                int gr = bm + wm + i * 16 + r;
                int gc = bn + wn + j * 16 + c;
                if (gc < N) {
                    float v = eb[e] + bias[gc];
                    if (EPI == EPI_RES)  v += extra[(size_t)gr * ldc + gc];
                    if (EPI == EPI_SILU) v = fsilu(v);
                    if (EPI == EPI_MUL)  v *= extra[(size_t)gr * ldc + gc];
                    if (OH) ((__half*)Cv)[(size_t)gr * ldc + gc] = __float2half(v);
                    else    ((float*)Cv)[(size_t)gr * ldc + gc] = v;
                }
            }
            __syncwarp();
        }
    }
}

// ---------------- Flash attention (fp16 mma, no P smem round-trip) -----------
#define AKLD 72
#define AK_ST (64 * AKLD)
#define ASMEM ((4 * AK_ST) * 2)

__global__ void __launch_bounds__(256) attn_kernel(
    const __half* __restrict__ qkv, __half* __restrict__ out)
{
    extern __shared__ __align__(16) char smc[];
    __half* Ks = (__half*)smc;
    __half* Vs = Ks + 2 * AK_ST;
    uint32_t sK = (uint32_t)__cvta_generic_to_shared(Ks);
    uint32_t sV = (uint32_t)__cvta_generic_to_shared(Vs);

    int tid = threadIdx.x, lane = tid & 31, warp = tid >> 5;
    int gid = lane >> 2, tig = lane & 3;
    int qt = 15 - blockIdx.x;
    int h  = blockIdx.y, bb = blockIdx.z;
    int q0 = qt * 128;
    int R  = warp * 16;
    const float LOG2E = 1.4426950408889634f;
    float qscale = 0.125f * LOG2E;
    float slope  = exp2f(-0.5f * (float)(h + 1)) * LOG2E;
    size_t base = (size_t)bb * TS * 3072;
    const __half* Qg = qkv + base + h * 64;
    const __half* Kg = Qg + 1024;
    const __half* Vg = Qg + 2048;

    int nkb = 2 * qt + 2;

    auto loadKV = [&](int kb) {
        int stg = kb & 1, k0 = kb * 64;
        #pragma unroll
        for (int j = 0; j < 2; j++) {
            int idx = tid + j * 256;
            int r = idx >> 3, c8 = (idx & 7) << 3;
            size_t go = (size_t)(k0 + r) * 3072 + c8;
            cp16(sK + (uint32_t)(stg * AK_ST + r * AKLD + c8) * 2u, Kg + go);
            cp16(sV + (uint32_t)(stg * AK_ST + r * AKLD + c8) * 2u, Vg + go);
        }
    };

    loadKV(0);
    CP_COMMIT();

    // Q fragments (scaled), rows R+gid / R+gid+8
    uint32_t qa[4][4];
    {
        const __half* Qr1 = Qg + (size_t)(q0 + R + gid) * 3072;
        const __half* Qr2 = Qr1 + 8 * 3072;
        #pragma unroll
        for (int kt = 0; kt < 4; kt++) {
            int d0 = kt * 16 + 2 * tig;
            qa[kt][0] = pkh2(__half2float(Qr1[d0]) * qscale, __half2float(Qr1[d0 + 1]) * qscale);
            qa[kt][1] = pkh2(__half2float(Qr2[d0]) * qscale, __half2float(Qr2[d0 + 1]) * qscale);
            qa[kt][2] = pkh2(__half2float(Qr1[d0 + 8]) * qscale, __half2float(Qr1[d0 + 9]) * qscale);
            qa[kt][3] = pkh2(__half2float(Qr2[d0 + 8]) * qscale, __half2float(Qr2[d0 + 9]) * qscale);
        }
    }

    float oa[8][4];
    #pragma unroll
    for (int nt = 0; nt < 8; nt++)
        #pragma unroll
        for (int e = 0; e < 4; e++) oa[nt][e] = 0.0f;
    float m1 = -1e30f, m2 = -1e30f, l1 = 0.0f, l2 = 0.0f;

    int qp1 = q0 + R + gid, qp2 = qp1 + 8;

    for (int kb = 0; kb < nkb; kb++) {
        if (kb + 1 < nkb) loadKV(kb + 1);
        CP_COMMIT();
        CP_WAIT1();
        __syncthreads();
        int k0 = kb * 64;
        const __half* K = Ks + (kb & 1) * AK_ST;
        uint32_t sVcur = sV + (uint32_t)((kb & 1) * AK_ST) * 2u;
        int vis = q0 + R + 15 - k0;

        if (vis >= 0) {
            int ntmax = vis >> 3;
            ntmax = (ntmax >= 7) ? 8 : (ntmax + 1);
            float sacc[8][4];
            #pragma unroll
            for (int nt = 0; nt < 8; nt++)
                #pragma unroll
                for (int e = 0; e < 4; e++) sacc[nt][e] = 0.0f;
            #pragma unroll
            for (int kt = 0; kt < 4; kt++) {
                #pragma unroll
                for (int nt = 0; nt < 8; nt++) {
                    if (nt < ntmax) {
                        const __half* kp = &K[(nt * 8 + gid) * AKLD + kt * 16 + 2 * tig];
                        uint32_t b0 = *(const uint32_t*)kp;
                        uint32_t b1 = *(const uint32_t*)(kp + 8);
                        mma16(sacc[nt], qa[kt], b0, b1);
                    }
                }
            }
            bool domask = (k0 + 63 > q0 + R);
            float mx1 = -1e30f, mx2 = -1e30f;
            #pragma unroll
            for (int nt = 0; nt < 8; nt++) {
                if (nt >= ntmax) continue;
                int kp0 = k0 + nt * 8 + tig * 2;
                float s0 = sacc[nt][0] + slope * (float)(qp1 - kp0);
                float s1 = sacc[nt][1] + slope * (float)(qp1 - kp0 - 1);
                float s2 = sacc[nt][2] + slope * (float)(qp2 - kp0);
                float s3 = sacc[nt][3] + slope * (float)(qp2 - kp0 - 1);
                if (domask) {
                    if (kp0     > qp1) s0 = -1e30f;
                    if (kp0 + 1 > qp1) s1 = -1e30f;
                    if (kp0     > qp2) s2 = -1e30f;
                    if (kp0 + 1 > qp2) s3 = -1e30f;
                }
                sacc[nt][0] = s0; sacc[nt][1] = s1; sacc[nt][2] = s2; sacc[nt][3] = s3;
                mx1 = fmaxf(mx1, fmaxf(s0, s1));
                mx2 = fmaxf(mx2, fmaxf(s2, s3));
            }
            mx1 = fmaxf(mx1, __shfl_xor_sync(0xffffffffu, mx1, 1));
            mx1 = fmaxf(mx1, __shfl_xor_sync(0xffffffffu, mx1, 2));
            mx2 = fmaxf(mx2, __shfl_xor_sync(0xffffffffu, mx2, 1));
            mx2 = fmaxf(mx2, __shfl_xor_sync(0xffffffffu, mx2, 2));
            float mn1 = fmaxf(m1, mx1), mn2 = fmaxf(m2, mx2);
            float f1 = fexp2(m1 - mn1), f2 = fexp2(m2 - mn2);
            float sum1 = 0.0f, sum2 = 0.0f;
            #pragma unroll
            for (int nt = 0; nt < 8; nt++) {
                if (nt >= ntmax) continue;
                float p0 = fexp2(sacc[nt][0] - mn1);
                float p1 = fexp2(sacc[nt][1] - mn1);
                float p2 = fexp2(sacc[nt][2] - mn2);
                float p3 = fexp2(sacc[nt][3] - mn2);
                sacc[nt][0] = p0; sacc[nt][1] = p1; sacc[nt][2] = p2; sacc[nt][3] = p3;
                sum1 += p0 + p1; sum2 += p2 + p3;
            }
            sum1 += __shfl_xor_sync(0xffffffffu, sum1, 1);
            sum1 += __shfl_xor_sync(0xffffffffu, sum1, 2);
            sum2 += __shfl_xor_sync(0xffffffffu, sum2, 1);
            sum2 += __shfl_xor_sync(0xffffffffu, sum2, 2);
            l1 = l1 * f1 + sum1;  l2 = l2 * f2 + sum2;
            m1 = mn1;  m2 = mn2;
            #pragma unroll
            for (int nt = 0; nt < 8; nt++) {
                oa[nt][0] *= f1; oa[nt][1] *= f1;
                oa[nt][2] *= f2; oa[nt][3] *= f2;
            }
            // O += P V : P converted reg->half2, V fragments via ldmatrix.trans
            int jmax = (ntmax + 1) >> 1;
            #pragma unroll
            for (int j = 0; j < 4; j++) {
                if (j >= jmax) continue;
                uint32_t pa[4];
                pa[0] = pkh2(sacc[2*j][0], sacc[2*j][1]);
                pa[1] = pkh2(sacc[2*j][2], sacc[2*j][3]);
                if (2*j + 1 < ntmax) {
                    pa[2] = pkh2(sacc[2*j+1][0], sacc[2*j+1][1]);
                    pa[3] = pkh2(sacc[2*j+1][2], sacc[2*j+1][3]);
                } else { pa[2] = 0u; pa[3] = 0u; }
                uint32_t rowa = sVcur + (uint32_t)((j * 16 + (lane & 15)) * AKLD) * 2u;
                #pragma unroll
                for (int nt = 0; nt < 8; nt++) {
                    uint32_t b0, b1;
                    ldsm_t2(b0, b1, rowa + (uint32_t)(nt * 8) * 2u);
                    mma16(oa[nt], pa, b0, b1);
                }
            }
        }
        __syncthreads();
    }

    float il1 = 1.0f / l1, il2 = 1.0f / l2;
    __half* Or1 = out + (size_t)(bb * TS + q0 + R + gid) * N_EMBD + h * 64;
    __half* Or2 = Or1 + 8 * N_EMBD;
    #pragma unroll
    for (int nt = 0; nt < 8; nt++) {
        *(uint32_t*)&Or1[nt * 8 + 2 * tig] = pkh2(oa[nt][0] * il1, oa[nt][1] * il1);
        *(uint32_t*)&Or2[nt * 8 + 2 * tig] = pkh2(oa[nt][2] * il2, oa[nt][3] * il2);
    }
}

// ---------------- launch -----------------------------------------------------
extern "C" void kernel_launch(void* const* d_in, const int* in_sizes, int n_in,
                              void* d_out, int out_size)
{
    (void)in_sizes; (void)n_in; (void)out_size;
    const float* x      = (const float*)d_in[0];
    const float* ln1_g  = (const float*)d_in[1];
    const float* ln1_b  = (const float*)d_in[2];
    const float* qkv_w  = (const float*)d_in[3];
    const float* qkv_b  = (const float*)d_in[4];
    const float* proj_w = (const float*)d_in[5];
    const float* proj_b = (const float*)d_in[6];
    const float* ln2_g  = (const float*)d_in[7];
    const float* ln2_b  = (const float*)d_in[8];
    const float* gate_w = (const float*)d_in[9];
    const float* gate_b = (const float*)d_in[10];
    const float* up_w   = (const float*)d_in[11];
    const float* up_b   = (const float*)d_in[12];
    const float* down_w = (const float*)d_in[13];
    const float* down_b = (const float*)d_in[14];
    float* out = (float*)d_out;

    __half *hh, *qkvh, *atth, *ffh, *qkvw, *projw, *downw, *wg, *wu;
    float *x2, *gate;
    cudaGetSymbolAddress((void**)&hh,    g_hh);
    cudaGetSymbolAddress((void**)&qkvh,  g_qkvh);
    cudaGetSymbolAddress((void**)&atth,  g_atth);
    cudaGetSymbolAddress((void**)&ffh,   g_ffh);
    cudaGetSymbolAddress((void**)&x2,    g_x2);
    cudaGetSymbolAddress((void**)&gate,  g_gate);
    cudaGetSymbolAddress((void**)&qkvw,  g_qkvw);
    cudaGetSymbolAddress((void**)&projw, g_projw);
    cudaGetSymbolAddress((void**)&downw, g_downw);
    cudaGetSymbolAddress((void**)&wg,    g_wg);
    cudaGetSymbolAddress((void**)&wu,    g_wu);

    cudaFuncSetAttribute(gemm_fp16<EPI_BIAS,1>, cudaFuncAttributeMaxDynamicSharedMemorySize, GSMEM);
    cudaFuncSetAttribute(gemm_fp16<EPI_RES, 0>, cudaFuncAttributeMaxDynamicSharedMemorySize, GSMEM);
    cudaFuncSetAttribute(gemm_fp16<EPI_SILU,0>, cudaFuncAttributeMaxDynamicSharedMemorySize, GSMEM);
    cudaFuncSetAttribute(gemm_fp16<EPI_MUL, 1>, cudaFuncAttributeMaxDynamicSharedMemorySize, GSMEM);
    cudaFuncSetAttribute(attn_kernel, cudaFuncAttributeMaxDynamicSharedMemorySize, ASMEM);

    // 0) convert weights to fp16
    conv_kernel<<<(N_EMBD * 3 * N_EMBD + 255) / 256, 256>>>(qkv_w, qkvw, N_EMBD * 3 * N_EMBD);
    conv_kernel<<<(N_EMBD * N_EMBD + 255) / 256, 256>>>(proj_w, projw, N_EMBD * N_EMBD);
    conv_kernel<<<(HID * N_EMBD + 255) / 256, 256>>>(down_w, downw, HID * N_EMBD);
    padconv_kernel<<<(N_EMBD * WP_LD + 255) / 256, 256>>>(gate_w, wg);
    padconv_kernel<<<(N_EMBD * WP_LD + 255) / 256, 256>>>(up_w, wu);

    // 1) LN1 -> half
    ln_kernel<<<BT, 256>>>(x, ln1_g, ln1_b, hh);
    // 2) qkv (half out)
    {
        dim3 g(3 * N_EMBD / 128, BT / 128);
        gemm_fp16<EPI_BIAS,1><<<g, 256, GSMEM>>>(hh, qkvw, qkv_b, nullptr, qkvh,
                                                 3 * N_EMBD, N_EMBD, N_EMBD, 3 * N_EMBD, 3 * N_EMBD);
    }
    // 3) attention (half out)
    {
        dim3 g(TS / 128, NHEAD, 2);
        attn_kernel<<<g, 256, ASMEM>>>(qkvh, atth);
    }
    // 4) x2 = att @ proj_w + b + x  (fp32 out)
    {
        dim3 g(N_EMBD / 128, BT / 128);
        gemm_fp16<EPI_RES,0><<<g, 256, GSMEM>>>(atth, projw, proj_b, x, x2,
                                                N_EMBD, N_EMBD, N_EMBD, N_EMBD, N_EMBD);
    }
    // 5) LN2 -> half
    ln_kernel<<<BT, 256>>>(x2, ln2_g, ln2_b, hh);
    // 6) gate = silu(h @ wg + b)  (fp32 out)
    {
        dim3 g(WP_LD / 128, BT / 128);
        gemm_fp16<EPI_SILU,0><<<g, 256, GSMEM>>>(hh, wg, gate_b, nullptr, gate,
                                                 HID, N_EMBD, N_EMBD, WP_LD, FF_LD);
        // 7) ff = (h @ wu + b) * gate  (half out)
        gemm_fp16<EPI_MUL,1><<<g, 256, GSMEM>>>(hh, wu, up_b, gate, ffh,
                                                HID, N_EMBD, N_EMBD, WP_LD, FF_LD);
    }
    // 8) out = ff @ down_w + b + x2  (fp32 out)
    {
        dim3 g(N_EMBD / 128, BT / 128);
        gemm_fp16<EPI_RES,0><<<g, 256, GSMEM>>>(ffh, downw, down_b, x2, out,
                                                N_EMBD, HID, FF_LD, N_EMBD, N_EMBD);
    }
}

// round 6
// speedup vs baseline: 5.7049x; 1.0568x over previous
#include <cuda_runtime.h>
#include <cuda_fp16.h>
#include <math.h>
#include <stdint.h>

#define N_EMBD 1024
#define NHEAD  16
#define HID    2730
#define FF_LD  2752
#define WP_LD  2816
#define BT     4096
#define TS     2048
#define LN_EPS 1e-5f

// ---------------- scratch ---------------------------------------------------
__device__ __half g_hh   [(size_t)BT * N_EMBD];
__device__ __half g_qkvh [(size_t)BT * 3 * N_EMBD];
__device__ __half g_atth [(size_t)BT * N_EMBD];
__device__ __half g_ffh  [(size_t)BT * FF_LD];    // pad cols stay zero (BSS, never stored)
__device__ __half g_gateh[(size_t)BT * FF_LD];    // pad cols stay zero
__device__ float  g_x2   [(size_t)BT * N_EMBD];
__device__ __half g_qkvw [(size_t)N_EMBD * 3 * N_EMBD];
__device__ __half g_projw[(size_t)N_EMBD * N_EMBD];
__device__ __half g_downw[(size_t)HID * N_EMBD];
__device__ __half g_wg   [(size_t)N_EMBD * WP_LD];
__device__ __half g_wu   [(size_t)N_EMBD * WP_LD];

// ---------------- helpers ----------------------------------------------------
__device__ __forceinline__ void cp16(uint32_t dst, const void* src) {
    asm volatile("cp.async.cg.shared.global [%0], [%1], 16;\n" :: "r"(dst), "l"(src));
}
__device__ __forceinline__ void cp16p(uint32_t dst, const void* src, int pb) {
    asm volatile("cp.async.cg.shared.global [%0], [%1], 16, %2;\n" :: "r"(dst), "l"(src), "r"(pb));
}
#define CP_COMMIT() asm volatile("cp.async.commit_group;\n")
#define CP_WAIT1()  asm volatile("cp.async.wait_group 1;\n")

__device__ __forceinline__ float fexp2(float t) {
    t = fmaxf(t, -126.0f);
    float r = t + 12582912.0f;
    int   fi = __float_as_int(r) - 0x4B400000;
    float f = t - (r - 12582912.0f);
    float p = 1.3333558e-3f;
    p = fmaf(p, f, 9.6181291e-3f);
    p = fmaf(p, f, 5.5504109e-2f);
    p = fmaf(p, f, 2.4022651e-1f);
    p = fmaf(p, f, 6.9314718e-1f);
    p = fmaf(p, f, 1.0f);
    return __int_as_float(__float_as_int(p) + (fi << 23));
}
__device__ __forceinline__ float fsilu(float v) {
    float e = fexp2(-fabsf(v) * 1.4426950408889634f);
    float d = 1.0f + e;
    float y = 1.4571429f - 0.45714286f * d;
    y = y * (2.0f - d * y);
    y = y * (2.0f - d * y);
    float sig = (v >= 0.0f) ? y : (1.0f - y);
    return v * sig;
}

__device__ __forceinline__ void mma16(float* c, const uint32_t* a, uint32_t b0, uint32_t b1) {
    asm volatile(
        "mma.sync.aligned.m16n8k16.row.col.f32.f16.f16.f32 "
        "{%0,%1,%2,%3}, {%4,%5,%6,%7}, {%8,%9}, {%0,%1,%2,%3};\n"
        : "+f"(c[0]), "+f"(c[1]), "+f"(c[2]), "+f"(c[3])
        : "r"(a[0]), "r"(a[1]), "r"(a[2]), "r"(a[3]), "r"(b0), "r"(b1));
}
__device__ __forceinline__ void ldsm4(uint32_t* r, uint32_t addr) {
    asm volatile("ldmatrix.sync.aligned.m8n8.x4.shared.b16 {%0,%1,%2,%3}, [%4];"
        : "=r"(r[0]), "=r"(r[1]), "=r"(r[2]), "=r"(r[3]) : "r"(addr));
}
__device__ __forceinline__ void ldsm4t(uint32_t* r, uint32_t addr) {
    asm volatile("ldmatrix.sync.aligned.m8n8.x4.trans.shared.b16 {%0,%1,%2,%3}, [%4];"
        : "=r"(r[0]), "=r"(r[1]), "=r"(r[2]), "=r"(r[3]) : "r"(addr));
}
__device__ __forceinline__ void ldsm_t2(uint32_t& r0, uint32_t& r1, uint32_t addr) {
    asm volatile("ldmatrix.sync.aligned.m8n8.x2.trans.shared.b16 {%0,%1}, [%2];"
        : "=r"(r0), "=r"(r1) : "r"(addr));
}
__device__ __forceinline__ uint32_t pkh2(float a, float b) {
    __half2 h = __floats2half2_rn(a, b);
    return *(uint32_t*)&h;
}

// ---------------- conversion kernels (vectorized) ----------------------------
__global__ void __launch_bounds__(256) conv_kernel(
    const float* __restrict__ w, __half* __restrict__ out, int n4)
{
    int idx = blockIdx.x * 256 + threadIdx.x;
    if (idx >= n4) return;
    float4 v = ((const float4*)w)[idx];
    uint2 u;
    u.x = pkh2(v.x, v.y);
    u.y = pkh2(v.z, v.w);
    ((uint2*)out)[idx] = u;
}
__global__ void __launch_bounds__(256) padconv_kernel(
    const float* __restrict__ w, __half* __restrict__ out)
{
    int idx = blockIdx.x * 256 + threadIdx.x;          // one half2 pair
    if (idx >= N_EMBD * (WP_LD / 2)) return;
    int row = idx / (WP_LD / 2);
    int col = (idx - row * (WP_LD / 2)) * 2;
    if (col < HID) {
        float2 v = *(const float2*)&w[(size_t)row * HID + col];
        ((uint32_t*)out)[idx] = pkh2(v.x, v.y);
    }
    // col >= HID: leave BSS zeros untouched
}

// ---------------- LayerNorm (fp32 in, half out) ------------------------------
__global__ void __launch_bounds__(256) ln_kernel(
    const float* __restrict__ x, const float* __restrict__ g,
    const float* __restrict__ b, __half* __restrict__ out)
{
    int row = blockIdx.x;
    int tid = threadIdx.x;
    const float4* xr = (const float4*)(x + (size_t)row * N_EMBD);
    float4 v = xr[tid];
    float s  = v.x + v.y + v.z + v.w;
    float ss = v.x*v.x + v.y*v.y + v.z*v.z + v.w*v.w;
    #pragma unroll
    for (int o = 16; o; o >>= 1) {
        s  += __shfl_xor_sync(0xffffffffu, s, o);
        ss += __shfl_xor_sync(0xffffffffu, ss, o);
    }
    __shared__ float red[16];
    int warp = tid >> 5, lane = tid & 31;
    if (lane == 0) { red[warp] = s; red[8 + warp] = ss; }
    __syncthreads();
    if (tid == 0) {
        float a = 0.f, a2 = 0.f;
        #pragma unroll
        for (int i = 0; i < 8; i++) { a += red[i]; a2 += red[8 + i]; }
        red[0] = a; red[8] = a2;
    }
    __syncthreads();
    float mean = red[0] * (1.0f / N_EMBD);
    float var  = red[8] * (1.0f / N_EMBD) - mean * mean;
    float rstd = rsqrtf(var + LN_EPS);
    float4 go = ((const float4*)g)[tid];
    float4 bo = ((const float4*)b)[tid];
    uint2 u;
    u.x = pkh2((v.x - mean) * rstd * go.x + bo.x, (v.y - mean) * rstd * go.y + bo.y);
    u.y = pkh2((v.z - mean) * rstd * go.z + bo.z, (v.w - mean) * rstd * go.w + bo.w);
    ((uint2*)(out + (size_t)row * N_EMBD))[tid] = u;
}

// ---------------- FP16 GEMM: raw mma + ldmatrix + register epilogue ----------
#define H_ALD 72
#define H_BLD 136
#define H_AST (128 * H_ALD)
#define H_BST (64 * H_BLD)
#define GSMEM ((2 * H_AST + 2 * H_BST) * 2)

enum { EPI_BIAS = 0, EPI_RES = 1, EPI_SILU = 2, EPI_MUL = 3 };

// EPI: epilogue; OH: output half; EH: extra is half
template <int EPI, int OH, int EH>
__global__ void __launch_bounds__(256, 2) gemm_fp16(
    const __half* __restrict__ A, const __half* __restrict__ B,
    const float* __restrict__ bias, const void* __restrict__ extra,
    void* __restrict__ Cv, int N, int K, int lda, int ldb, int ldc)
{
    extern __shared__ __align__(16) char smc[];
    __half* As = (__half*)smc;
    __half* Bs = As + 2 * H_AST;
    uint32_t sA = (uint32_t)__cvta_generic_to_shared(As);
    uint32_t sB = (uint32_t)__cvta_generic_to_shared(Bs);

    int tid = threadIdx.x;
    int warp = tid >> 5, lane = tid & 31;
    int gid = lane >> 2, tig = lane & 3;
    int bm = blockIdx.y * 128, bn = blockIdx.x * 128;
    int wm = (warp >> 2) * 64, wn = (warp & 3) * 32;
    int nkt = (K + 63) >> 6;

    float acc[4][4][4];
    #pragma unroll
    for (int m = 0; m < 4; m++)
        #pragma unroll
        for (int n = 0; n < 4; n++)
            #pragma unroll
            for (int e = 0; e < 4; e++) acc[m][n][e] = 0.0f;

    // ldmatrix lane addressing
    int l8 = lane & 7, quad = lane >> 3;
    int mrow = (quad & 1) * 8 + l8;        // row within 16
    int mcol = (quad >> 1) * 8;            // col within 16
    uint32_t aoff[4], boff[2];
    #pragma unroll
    for (int m = 0; m < 4; m++)
        aoff[m] = (uint32_t)(((wm + m * 16 + mrow) * H_ALD + mcol) * 2);
    #pragma unroll
    for (int p = 0; p < 2; p++)
        boff[p] = (uint32_t)((mrow * H_BLD + wn + p * 16 + mcol) * 2);

    auto loadT = [&](int kt) {
        int stg = kt & 1;
        int k0 = kt << 6;
        #pragma unroll
        for (int j = 0; j < 4; j++) {
            int idx = tid + j * 256;
            int r = idx >> 3, c8 = (idx & 7) << 3;
            uint32_t dst = sA + (uint32_t)(stg * H_AST + r * H_ALD + c8) * 2u;
            cp16(dst, A + (size_t)(bm + r) * lda + k0 + c8);
        }
        #pragma unroll
        for (int j = 0; j < 4; j++) {
            int idx = tid + j * 256;
            int r = idx >> 4, c8 = (idx & 15) << 3;
            int kk = k0 + r;
            int pb = (kk < K) ? 16 : 0;
            uint32_t dst = sB + (uint32_t)(stg * H_BST + r * H_BLD + c8) * 2u;
            cp16p(dst, B + (size_t)kk * ldb + bn + c8, pb);
        }
    };

    loadT(0);
    CP_COMMIT();
    for (int kt = 0; kt < nkt; kt++) {
        if (kt + 1 < nkt) loadT(kt + 1);
        CP_COMMIT();
        CP_WAIT1();
        __syncthreads();
        uint32_t aBase = sA + (uint32_t)((kt & 1) * H_AST) * 2u;
        uint32_t bBase = sB + (uint32_t)((kt & 1) * H_BST) * 2u;
        #pragma unroll
        for (int ks = 0; ks < 4; ks++) {
            uint32_t a[4][4], bb[2][4];
            #pragma unroll
            for (int m = 0; m < 4; m++)
                ldsm4(a[m], aBase + aoff[m] + (uint32_t)(ks * 32));
            #pragma unroll
            for (int p = 0; p < 2; p++)
                ldsm4t(bb[p], bBase + boff[p] + (uint32_t)(ks * 16 * H_BLD * 2));
            #pragma unroll
            for (int m = 0; m < 4; m++) {
                #pragma unroll
                for (int p = 0; p < 2; p++) {
                    mma16(acc[m][p * 2],     a[m], bb[p][0], bb[p][1]);
                    mma16(acc[m][p * 2 + 1], a[m], bb[p][2], bb[p][3]);
                }
            }
        }
        __syncthreads();
    }

    // register epilogue, paired-column stores
    #pragma unroll
    for (int m = 0; m < 4; m++) {
        int gr = bm + wm + m * 16 + gid;
        #pragma unroll
        for (int n = 0; n < 4; n++) {
            int gc = bn + wn + n * 8 + 2 * tig;
            if (gc < N) {
                float2 bi = *(const float2*)&bias[gc];
                float v0 = acc[m][n][0] + bi.x;
                float v1 = acc[m][n][1] + bi.y;
                float v2 = acc[m][n][2] + bi.x;
                float v3 = acc[m][n][3] + bi.y;
                if (EPI == EPI_RES) {
                    const float* ex = (const float*)extra;
                    float2 e0 = *(const float2*)&ex[(size_t)gr * ldc + gc];
                    float2 e1 = *(const float2*)&ex[(size_t)(gr + 8) * ldc + gc];
                    v0 += e0.x; v1 += e0.y; v2 += e1.x; v3 += e1.y;
                }
                if (EPI == EPI_SILU) {
                    v0 = fsilu(v0); v1 = fsilu(v1); v2 = fsilu(v2); v3 = fsilu(v3);
                }
                if (EPI == EPI_MUL) {
                    if (EH) {
                        const __half* ex = (const __half*)extra;
                        __half2 h0 = *(const __half2*)&ex[(size_t)gr * ldc + gc];
                        __half2 h1 = *(const __half2*)&ex[(size_t)(gr + 8) * ldc + gc];
                        float2 e0 = __half22float2(h0), e1 = __half22float2(h1);
                        v0 *= e0.x; v1 *= e0.y; v2 *= e1.x; v3 *= e1.y;
                    } else {
                        const float* ex = (const float*)extra;
                        float2 e0 = *(const float2*)&ex[(size_t)gr * ldc + gc];
                        float2 e1 = *(const float2*)&ex[(size_t)(gr + 8) * ldc + gc];
                        v0 *= e0.x; v1 *= e0.y; v2 *= e1.x; v3 *= e1.y;
                    }
                }
                if (OH) {
                    __half* C = (__half*)Cv;
                    *(uint32_t*)&C[(size_t)gr * ldc + gc]       = pkh2(v0, v1);
                    *(uint32_t*)&C[(size_t)(gr + 8) * ldc + gc] = pkh2(v2, v3);
                } else {
                    float* C = (float*)Cv;
                    *(float2*)&C[(size_t)gr * ldc + gc]       = make_float2(v0, v1);
                    *(float2*)&C[(size_t)(gr + 8) * ldc + gc] = make_float2(v2, v3);
                }
            }
        }
    }
}

// ---------------- Flash attention (fp16 mma, P in registers) -----------------
#define AKLD 72
#define AK_ST (64 * AKLD)
#define ASMEM ((4 * AK_ST) * 2)

__global__ void __launch_bounds__(256) attn_kernel(
    const __half* __restrict__ qkv, __half* __restrict__ out)
{
    extern __shared__ __align__(16) char smc[];
    __half* Ks = (__half*)smc;
    __half* Vs = Ks + 2 * AK_ST;
    uint32_t sK = (uint32_t)__cvta_generic_to_shared(Ks);
    uint32_t sV = (uint32_t)__cvta_generic_to_shared(Vs);

    int tid = threadIdx.x, lane = tid & 31, warp = tid >> 5;
    int gid = lane >> 2, tig = lane & 3;
    int qt = 15 - blockIdx.x;
    int h  = blockIdx.y, bb = blockIdx.z;
    int q0 = qt * 128;
    int R  = warp * 16;
    const float LOG2E = 1.4426950408889634f;
    float qscale = 0.125f * LOG2E;
    float slope  = exp2f(-0.5f * (float)(h + 1)) * LOG2E;
    size_t base = (size_t)bb * TS * 3072;
    const __half* Qg = qkv + base + h * 64;
    const __half* Kg = Qg + 1024;
    const __half* Vg = Qg + 2048;

    int nkb = 2 * qt + 2;

    auto loadKV = [&](int kb) {
        int stg = kb & 1, k0 = kb * 64;
        #pragma unroll
        for (int j = 0; j < 2; j++) {
            int idx = tid + j * 256;
            int r = idx >> 3, c8 = (idx & 7) << 3;
            size_t go = (size_t)(k0 + r) * 3072 + c8;
            cp16(sK + (uint32_t)(stg * AK_ST + r * AKLD + c8) * 2u, Kg + go);
            cp16(sV + (uint32_t)(stg * AK_ST + r * AKLD + c8) * 2u, Vg + go);
        }
    };

    loadKV(0);
    CP_COMMIT();

    uint32_t qa[4][4];
    {
        const __half* Qr1 = Qg + (size_t)(q0 + R + gid) * 3072;
        const __half* Qr2 = Qr1 + 8 * 3072;
        #pragma unroll
        for (int kt = 0; kt < 4; kt++) {
            int d0 = kt * 16 + 2 * tig;
            qa[kt][0] = pkh2(__half2float(Qr1[d0]) * qscale, __half2float(Qr1[d0 + 1]) * qscale);
            qa[kt][1] = pkh2(__half2float(Qr2[d0]) * qscale, __half2float(Qr2[d0 + 1]) * qscale);
            qa[kt][2] = pkh2(__half2float(Qr1[d0 + 8]) * qscale, __half2float(Qr1[d0 + 9]) * qscale);
            qa[kt][3] = pkh2(__half2float(Qr2[d0 + 8]) * qscale, __half2float(Qr2[d0 + 9]) * qscale);
        }
    }

    float oa[8][4];
    #pragma unroll
    for (int nt = 0; nt < 8; nt++)
        #pragma unroll
        for (int e = 0; e < 4; e++) oa[nt][e] = 0.0f;
    float m1 = -1e30f, m2 = -1e30f, l1 = 0.0f, l2 = 0.0f;

    int qp1 = q0 + R + gid, qp2 = qp1 + 8;

    for (int kb = 0; kb < nkb; kb++) {
        if (kb + 1 < nkb) loadKV(kb + 1);
        CP_COMMIT();
        CP_WAIT1();
        __syncthreads();
        int k0 = kb * 64;
        const __half* K = Ks + (kb & 1) * AK_ST;
        uint32_t sVcur = sV + (uint32_t)((kb & 1) * AK_ST) * 2u;
        int vis = q0 + R + 15 - k0;

        if (vis >= 0) {
            int ntmax = vis >> 3;
            ntmax = (ntmax >= 7) ? 8 : (ntmax + 1);
            float sacc[8][4];
            #pragma unroll
            for (int nt = 0; nt < 8; nt++)
                #pragma unroll
                for (int e = 0; e < 4; e++) sacc[nt][e] = 0.0f;
            #pragma unroll
            for (int kt = 0; kt < 4; kt++) {
                #pragma unroll
                for (int nt = 0; nt < 8; nt++) {
                    if (nt < ntmax) {
                        const __half* kp = &K[(nt * 8 + gid) * AKLD + kt * 16 + 2 * tig];
                        uint32_t b0 = *(const uint32_t*)kp;
                        uint32_t b1 = *(const uint32_t*)(kp + 8);
                        mma16(sacc[nt], qa[kt], b0, b1);
                    }
                }
            }
            bool domask = (k0 + 63 > q0 + R);
            float mx1 = -1e30f, mx2 = -1e30f;
            #pragma unroll
            for (int nt = 0; nt < 8; nt++) {
                if (nt >= ntmax) continue;
                int kp0 = k0 + nt * 8 + tig * 2;
                float s0 = sacc[nt][0] + slope * (float)(qp1 - kp0);
                float s1 = sacc[nt][1] + slope * (float)(qp1 - kp0 - 1);
                float s2 = sacc[nt][2] + slope * (float)(qp2 - kp0);
                float s3 = sacc[nt][3] + slope * (float)(qp2 - kp0 - 1);
                if (domask) {
                    if (kp0     > qp1) s0 = -1e30f;
                    if (kp0 + 1 > qp1) s1 = -1e30f;
                    if (kp0     > qp2) s2 = -1e30f;
                    if (kp0 + 1 > qp2) s3 = -1e30f;
                }
                sacc[nt][0] = s0; sacc[nt][1] = s1; sacc[nt][2] = s2; sacc[nt][3] = s3;
                mx1 = fmaxf(mx1, fmaxf(s0, s1));
                mx2 = fmaxf(mx2, fmaxf(s2, s3));
            }
            mx1 = fmaxf(mx1, __shfl_xor_sync(0xffffffffu, mx1, 1));
            mx1 = fmaxf(mx1, __shfl_xor_sync(0xffffffffu, mx1, 2));
            mx2 = fmaxf(mx2, __shfl_xor_sync(0xffffffffu, mx2, 1));
            mx2 = fmaxf(mx2, __shfl_xor_sync(0xffffffffu, mx2, 2));
            float mn1 = fmaxf(m1, mx1), mn2 = fmaxf(m2, mx2);
            float f1 = fexp2(m1 - mn1), f2 = fexp2(m2 - mn2);
            float sum1 = 0.0f, sum2 = 0.0f;
            #pragma unroll
            for (int nt = 0; nt < 8; nt++) {
                if (nt >= ntmax) continue;
                float p0 = fexp2(sacc[nt][0] - mn1);
                float p1 = fexp2(sacc[nt][1] - mn1);
                float p2 = fexp2(sacc[nt][2] - mn2);
                float p3 = fexp2(sacc[nt][3] - mn2);
                sacc[nt][0] = p0; sacc[nt][1] = p1; sacc[nt][2] = p2; sacc[nt][3] = p3;
                sum1 += p0 + p1; sum2 += p2 + p3;
            }
            sum1 += __shfl_xor_sync(0xffffffffu, sum1, 1);
            sum1 += __shfl_xor_sync(0xffffffffu, sum1, 2);
            sum2 += __shfl_xor_sync(0xffffffffu, sum2, 1);
            sum2 += __shfl_xor_sync(0xffffffffu, sum2, 2);
            l1 = l1 * f1 + sum1;  l2 = l2 * f2 + sum2;
            m1 = mn1;  m2 = mn2;
            #pragma unroll
            for (int nt = 0; nt < 8; nt++) {
                oa[nt][0] *= f1; oa[nt][1] *= f1;
                oa[nt][2] *= f2; oa[nt][3] *= f2;
            }
            int jmax = (ntmax + 1) >> 1;
            #pragma unroll
            for (int j = 0; j < 4; j++) {
                if (j >= jmax) continue;
                uint32_t pa[4];
                pa[0] = pkh2(sacc[2*j][0], sacc[2*j][1]);
                pa[1] = pkh2(sacc[2*j][2], sacc[2*j][3]);
                if (2*j + 1 < ntmax) {
                    pa[2] = pkh2(sacc[2*j+1][0], sacc[2*j+1][1]);
                    pa[3] = pkh2(sacc[2*j+1][2], sacc[2*j+1][3]);
                } else { pa[2] = 0u; pa[3] = 0u; }
                uint32_t rowa = sVcur + (uint32_t)((j * 16 + (lane & 15)) * AKLD) * 2u;
                #pragma unroll
                for (int nt = 0; nt < 8; nt++) {
                    uint32_t b0, b1;
                    ldsm_t2(b0, b1, rowa + (uint32_t)(nt * 8) * 2u);
                    mma16(oa[nt], pa, b0, b1);
                }
            }
        }
        __syncthreads();
    }

    float il1 = 1.0f / l1, il2 = 1.0f / l2;
    __half* Or1 = out + (size_t)(bb * TS + q0 + R + gid) * N_EMBD + h * 64;
    __half* Or2 = Or1 + 8 * N_EMBD;
    #pragma unroll
    for (int nt = 0; nt < 8; nt++) {
        *(uint32_t*)&Or1[nt * 8 + 2 * tig] = pkh2(oa[nt][0] * il1, oa[nt][1] * il1);
        *(uint32_t*)&Or2[nt * 8 + 2 * tig] = pkh2(oa[nt][2] * il2, oa[nt][3] * il2);
    }
}

// ---------------- launch -----------------------------------------------------
extern "C" void kernel_launch(void* const* d_in, const int* in_sizes, int n_in,
                              void* d_out, int out_size)
{
    (void)in_sizes; (void)n_in; (void)out_size;
    const float* x      = (const float*)d_in[0];
    const float* ln1_g  = (const float*)d_in[1];
    const float* ln1_b  = (const float*)d_in[2];
    const float* qkv_w  = (const float*)d_in[3];
    const float* qkv_b  = (const float*)d_in[4];
    const float* proj_w = (const float*)d_in[5];
    const float* proj_b = (const float*)d_in[6];
    const float* ln2_g  = (const float*)d_in[7];
    const float* ln2_b  = (const float*)d_in[8];
    const float* gate_w = (const float*)d_in[9];
    const float* gate_b = (const float*)d_in[10];
    const float* up_w   = (const float*)d_in[11];
    const float* up_b   = (const float*)d_in[12];
    const float* down_w = (const float*)d_in[13];
    const float* down_b = (const float*)d_in[14];
    float* out = (float*)d_out;

    __half *hh, *qkvh, *atth, *ffh, *gateh, *qkvw, *projw, *downw, *wg, *wu;
    float *x2;
    cudaGetSymbolAddress((void**)&hh,    g_hh);
    cudaGetSymbolAddress((void**)&qkvh,  g_qkvh);
    cudaGetSymbolAddress((void**)&atth,  g_atth);
    cudaGetSymbolAddress((void**)&ffh,   g_ffh);
    cudaGetSymbolAddress((void**)&gateh, g_gateh);
    cudaGetSymbolAddress((void**)&x2,    g_x2);
    cudaGetSymbolAddress((void**)&qkvw,  g_qkvw);
    cudaGetSymbolAddress((void**)&projw, g_projw);
    cudaGetSymbolAddress((void**)&downw, g_downw);
    cudaGetSymbolAddress((void**)&wg,    g_wg);
    cudaGetSymbolAddress((void**)&wu,    g_wu);

    cudaFuncSetAttribute(gemm_fp16<EPI_BIAS,1,0>, cudaFuncAttributeMaxDynamicSharedMemorySize, GSMEM);
    cudaFuncSetAttribute(gemm_fp16<EPI_RES, 0,0>, cudaFuncAttributeMaxDynamicSharedMemorySize, GSMEM);
    cudaFuncSetAttribute(gemm_fp16<EPI_SILU,1,0>, cudaFuncAttributeMaxDynamicSharedMemorySize, GSMEM);
    cudaFuncSetAttribute(gemm_fp16<EPI_MUL, 1,1>, cudaFuncAttributeMaxDynamicSharedMemorySize, GSMEM);
    cudaFuncSetAttribute(attn_kernel, cudaFuncAttributeMaxDynamicSharedMemorySize, ASMEM);

    // 0) convert weights
    conv_kernel<<<(N_EMBD * 3 * N_EMBD / 4 + 255) / 256, 256>>>(qkv_w, qkvw, N_EMBD * 3 * N_EMBD / 4);
    conv_kernel<<<(N_EMBD * N_EMBD / 4 + 255) / 256, 256>>>(proj_w, projw, N_EMBD * N_EMBD / 4);
    conv_kernel<<<(HID * N_EMBD / 4 + 255) / 256, 256>>>(down_w, downw, HID * N_EMBD / 4);
    padconv_kernel<<<(N_EMBD * WP_LD / 2 + 255) / 256, 256>>>(gate_w, wg);
    padconv_kernel<<<(N_EMBD * WP_LD / 2 + 255) / 256, 256>>>(up_w, wu);

    // 1) LN1
    ln_kernel<<<BT, 256>>>(x, ln1_g, ln1_b, hh);
    // 2) qkv
    {
        dim3 g(3 * N_EMBD / 128, BT / 128);
        gemm_fp16<EPI_BIAS,1,0><<<g, 256, GSMEM>>>(hh, qkvw, qkv_b, nullptr, qkvh,
                                                   3 * N_EMBD, N_EMBD, N_EMBD, 3 * N_EMBD, 3 * N_EMBD);
    }
    // 3) attention
    {
        dim3 g(TS / 128, NHEAD, 2);
        attn_kernel<<<g, 256, ASMEM>>>(qkvh, atth);
    }
    // 4) x2 = att @ proj_w + b + x
    {
        dim3 g(N_EMBD / 128, BT / 128);
        gemm_fp16<EPI_RES,0,0><<<g, 256, GSMEM>>>(atth, projw, proj_b, x, x2,
                                                  N_EMBD, N_EMBD, N_EMBD, N_EMBD, N_EMBD);
    }
    // 5) LN2
    ln_kernel<<<BT, 256>>>(x2, ln2_g, ln2_b, hh);
    // 6) gate = silu(h @ wg + b)  -> half
    {
        dim3 g(WP_LD / 128, BT / 128);
        gemm_fp16<EPI_SILU,1,0><<<g, 256, GSMEM>>>(hh, wg, gate_b, nullptr, gateh,
                                                   HID, N_EMBD, N_EMBD, WP_LD, FF_LD);
        // 7) ff = (h @ wu + b) * gate -> half
        gemm_fp16<EPI_MUL,1,1><<<g, 256, GSMEM>>>(hh, wu, up_b, gateh, ffh,
                                                  HID, N_EMBD, N_EMBD, WP_LD, FF_LD);
    }
    // 8) out = ff @ down_w + b + x2
    {
        dim3 g(N_EMBD / 128, BT / 128);
        gemm_fp16<EPI_RES,0,0><<<g, 256, GSMEM>>>(ffh, downw, down_b, x2, out,
                                                  N_EMBD, HID, FF_LD, N_EMBD, N_EMBD);
    }
}